// round 14
// baseline (speedup 1.0000x reference)
#include <cuda_runtime.h>
#include <cuda_bf16.h>
#include <math.h>

#define NB   1024
#define NNUM 16
#define NCAT 16
#define NCH  32
#define NH   64
#define NV   100
#define KSEL 8
#define EPS  1e-5f

// ---------------- scratch (static device globals; no allocs) ----------------
__device__ float g_fe3[NB * NCH * NH];            // 8MB
__device__ float g_impraw[NB * NCH];
__device__ float g_p[NB * NCH];
__device__ int   g_idx[NB * KSEL];
__device__ int   g_cnt[NCH];
__device__ int   g_nodes[NCH * NB];
__device__ int   g_loc[NCH * NB];
__device__ float g_Y[NB * NH];
__device__ float g_adj[(size_t)NCH * NB * NB];    // slab: E=exp(S), diag 0
__device__ float g_rowsum[NCH * NB];
__device__ float g_Z[NCH];
__device__ float g_X1[NCH * NB * NH];             // GCN layer-1 output (post-relu)
__device__ float g_T[NCH * NB * NH];              // GCN layer-2 output X2 (post-relu)
__device__ float g_stats1[NCH * 2];
__device__ float g_stats2[NCH * 2];
__device__ float g_sums[8];
__device__ float g_part[32 * NB * NH];            // 8MB split-K partial slabs

// ---------------------------------------------------------------------------
__global__ void k_init() {
  int i = threadIdx.x;
  if (i < 8) g_sums[i] = 0.f;
  if (i < NCH) { g_cnt[i] = 0; g_Z[i] = 0.f; }
  if (i < NCH * 2) { g_stats1[i] = 0.f; g_stats2[i] = 0.f; }
}

__global__ void k_fe(const float* __restrict__ num_data, const int* __restrict__ cat_data,
                     const float* __restrict__ num_w, const float* __restrict__ num_b,
                     const float* __restrict__ cat_emb) {
  int t = threadIdx.x;
  int b = blockIdx.x >> 1;
  int half = blockIdx.x & 1;
  float s = 0.f, s2 = 0.f;
#pragma unroll
  for (int q = 0; q < 4; q++) {
    int off = t + q * 256;
    int ch = off >> 6, h = off & 63;
    float v;
    if (half == 0) {
      v = num_data[b * NNUM + ch] * num_w[ch * NH + h] + num_b[ch * NH + h];
      v = fmaxf(v, 0.f);
    } else {
      v = cat_emb[((size_t)ch * NV + cat_data[b * NCAT + ch]) * NH + h];
    }
    g_fe3[b * 2048 + half * 1024 + off] = v;
    s += v; s2 += v * v;
  }
#pragma unroll
  for (int o = 16; o; o >>= 1) {
    s  += __shfl_down_sync(0xffffffffu, s, o);
    s2 += __shfl_down_sync(0xffffffffu, s2, o);
  }
  __shared__ float red[16];
  if ((t & 31) == 0) { red[(t >> 5) * 2] = s; red[(t >> 5) * 2 + 1] = s2; }
  __syncthreads();
  if (t == 0) {
    float ts = 0.f, ts2 = 0.f;
    for (int w = 0; w < 8; w++) { ts += red[w * 2]; ts2 += red[w * 2 + 1]; }
    atomicAdd(&g_sums[half * 2], ts);
    atomicAdd(&g_sums[half * 2 + 1], ts2);
  }
}

// Register-tiled interact (one row b per block, 128 threads, 4x4 micro-tile).
__global__ void k_interact(const float* __restrict__ w1, const float* __restrict__ b1,
                           const float* __restrict__ gg, const float* __restrict__ be,
                           const float* __restrict__ w2, const float* __restrict__ b2f) {
  int b = blockIdx.x;
  int t = threadIdx.x;             // 128
  int cg = t >> 4, hg = t & 15;
  __shared__ float xsT[64][36];
  __shared__ float w1s[64][68];
  __shared__ float impsh[8][2];
  const float invN = 1.f / 1048576.f;
  float mu0 = g_sums[0] * invN;
  float rs0 = rsqrtf(g_sums[1] * invN - mu0 * mu0 + EPS);
  float mu1 = g_sums[2] * invN;
  float rs1 = rsqrtf(g_sums[3] * invN - mu1 * mu1 + EPS);
  for (int e = t; e < 4096; e += 128) w1s[e >> 6][e & 63] = w1[e];
  for (int e = t; e < 2048; e += 128) {
    int c = e >> 6, i = e & 63;
    float v = g_fe3[b * 2048 + e];
    xsT[i][c] = (c < 16) ? (v - mu0) * rs0 : (v - mu1) * rs1;
  }
  __syncthreads();
  float acc[4][4];
#pragma unroll
  for (int x = 0; x < 4; x++)
#pragma unroll
    for (int y = 0; y < 4; y++) acc[x][y] = 0.f;
#pragma unroll 16
  for (int kk = 0; kk < 64; kk++) {
    float4 a = *(const float4*)&xsT[kk][cg * 4];
    float4 w = *(const float4*)&w1s[kk][hg * 4];
    acc[0][0] += a.x * w.x; acc[0][1] += a.x * w.y; acc[0][2] += a.x * w.z; acc[0][3] += a.x * w.w;
    acc[1][0] += a.y * w.x; acc[1][1] += a.y * w.y; acc[1][2] += a.y * w.z; acc[1][3] += a.y * w.w;
    acc[2][0] += a.z * w.x; acc[2][1] += a.z * w.y; acc[2][2] += a.z * w.z; acc[2][3] += a.z * w.w;
    acc[3][0] += a.w * w.x; acc[3][1] += a.w * w.y; acc[3][2] += a.w * w.z; acc[3][3] += a.w * w.w;
  }
  int h0 = hg * 4;
  float4 b1v = *(const float4*)&b1[h0];
  float4 ggv = *(const float4*)&gg[h0];
  float4 bev = *(const float4*)&be[h0];
  float4 w2v = *(const float4*)&w2[h0];
  float b2v = b2f[0];
  float simp = 0.f, simp2 = 0.f;
#pragma unroll
  for (int x = 0; x < 4; x++) {
    float v0 = fmaxf(acc[x][0] + b1v.x, 0.f);
    float v1 = fmaxf(acc[x][1] + b1v.y, 0.f);
    float v2 = fmaxf(acc[x][2] + b1v.z, 0.f);
    float v3 = fmaxf(acc[x][3] + b1v.w, 0.f);
    float s  = v0 + v1 + v2 + v3;
    float s2 = v0 * v0 + v1 * v1 + v2 * v2 + v3 * v3;
#pragma unroll
    for (int o = 8; o; o >>= 1) {
      s  += __shfl_down_sync(0xffffffffu, s, o, 16);
      s2 += __shfl_down_sync(0xffffffffu, s2, o, 16);
    }
    s  = __shfl_sync(0xffffffffu, s, 0, 16);
    s2 = __shfl_sync(0xffffffffu, s2, 0, 16);
    float mu = s * (1.f / 64.f);
    float var = s2 * (1.f / 64.f) - mu * mu;
    float rstd = rsqrtf(var + EPS);
    float pp = ((v0 - mu) * rstd * ggv.x + bev.x) * w2v.x
             + ((v1 - mu) * rstd * ggv.y + bev.y) * w2v.y
             + ((v2 - mu) * rstd * ggv.z + bev.z) * w2v.z
             + ((v3 - mu) * rstd * ggv.w + bev.w) * w2v.w;
#pragma unroll
    for (int o = 8; o; o >>= 1) pp += __shfl_down_sync(0xffffffffu, pp, o, 16);
    if (hg == 0) {
      float val = pp + b2v;
      g_impraw[b * 32 + cg * 4 + x] = val;
      simp += val; simp2 += val * val;
    }
  }
  if (hg == 0) { impsh[cg][0] = simp; impsh[cg][1] = simp2; }
  __syncthreads();
  if (t == 0) {
    float a = 0.f, bsq = 0.f;
    for (int w = 0; w < 8; w++) { a += impsh[w][0]; bsq += impsh[w][1]; }
    atomicAdd(&g_sums[4], a);
    atomicAdd(&g_sums[5], bsq);
  }
}

// warp0 top-8 + softmax + idx; all warps stream fe3 concurrently.
__global__ void k_topk() {
  int b = blockIdx.x;
  int t = threadIdx.x;  // 256
  const float inv = 1.f / (NB * NCH);
  float mui = g_sums[4] * inv;
  float rsi = rsqrtf(g_sums[5] * inv - mui * mui + EPS);
  if (t < 32) {
    float imp = (g_impraw[b * 32 + t] - mui) * rsi;
    float v = imp;
    float mx0 = 0.f;
#pragma unroll
    for (int k = 0; k < KSEL; k++) {
      float m = v; int mi = t;
#pragma unroll
      for (int o = 16; o; o >>= 1) {
        float om = __shfl_down_sync(0xffffffffu, m, o);
        int   oi = __shfl_down_sync(0xffffffffu, mi, o);
        if (om > m) { m = om; mi = oi; }
      }
      m  = __shfl_sync(0xffffffffu, m, 0);
      mi = __shfl_sync(0xffffffffu, mi, 0);
      if (k == 0) mx0 = m;
      if (t == mi) v = -1e30f;
    }
    bool chosen = (v == -1e30f);
    float e = chosen ? __expf(imp - mx0) : 0.f;
    float es = e;
#pragma unroll
    for (int o = 16; o; o >>= 1) es += __shfl_xor_sync(0xffffffffu, es, o);
    g_p[b * 32 + t] = e / es;
    unsigned bal = __ballot_sync(0xffffffffu, chosen);
    if (chosen) {
      int rank = __popc(bal & ((1u << t) - 1u));
      g_idx[b * KSEL + rank] = t;   // ascending by construction
    }
  }
  const float invN = 1.f / 1048576.f;
  float mu0 = g_sums[0] * invN;
  float rs0 = rsqrtf(g_sums[1] * invN - mu0 * mu0 + EPS);
  float mu1 = g_sums[2] * invN;
  float rs1 = rsqrtf(g_sums[3] * invN - mu1 * mu1 + EPS);
  float4* p4 = (float4*)&g_fe3[b * 2048];
#pragma unroll
  for (int k = 0; k < 2; k++) {
    int q4 = t + k * 256;                  // 0..511
    int ch = q4 >> 4;
    float impv = (g_impraw[b * 32 + ch] - mui) * rsi;
    float mu = (q4 < 256) ? mu0 : mu1;
    float rs = (q4 < 256) ? rs0 : rs1;
    float4 x = p4[q4];
    x.x = (x.x - mu) * rs * impv;
    x.y = (x.y - mu) * rs * impv;
    x.z = (x.z - mu) * rs * impv;
    x.w = (x.w - mu) * rs * impv;
    p4[q4] = x;
  }
}

// ---------------- shared GEMM body on raw shared pointers -------------------
__device__ __forceinline__ void gemm_run(const float* __restrict__ A, int lda, int Kd,
                                         const float* __restrict__ W,
                                         int m, int y, int slab, int stride,
                                         float* __restrict__ As, float* __restrict__ Ws) {
  int t = threadIdx.x;      // 256
  int m0 = m * 64;
  int r0 = (t >> 4) * 4;
  int c0 = (t & 15) * 4;
  float acc[4][4];
#pragma unroll
  for (int x = 0; x < 4; x++)
#pragma unroll
    for (int yy = 0; yy < 4; yy++) acc[x][yy] = 0.f;
  for (int ch = y; ch * 64 < Kd; ch += stride) {
    int k0 = ch * 64;
    for (int e = t; e < 4096; e += 256) {
      int r = e >> 6, kk = e & 63;
      As[r * 65 + kk] = A[(size_t)(m0 + r) * lda + k0 + kk];
      Ws[r * 68 + kk] = W[(size_t)(k0 + r) * 64 + kk];
    }
    __syncthreads();
#pragma unroll 8
    for (int kk = 0; kk < 64; kk++) {
      float a0 = As[r0 * 65 + kk], a1 = As[(r0 + 1) * 65 + kk];
      float a2 = As[(r0 + 2) * 65 + kk], a3 = As[(r0 + 3) * 65 + kk];
      float4 w = *(const float4*)&Ws[kk * 68 + c0];
      acc[0][0] += a0 * w.x; acc[0][1] += a0 * w.y; acc[0][2] += a0 * w.z; acc[0][3] += a0 * w.w;
      acc[1][0] += a1 * w.x; acc[1][1] += a1 * w.y; acc[1][2] += a1 * w.z; acc[1][3] += a1 * w.w;
      acc[2][0] += a2 * w.x; acc[2][1] += a2 * w.y; acc[2][2] += a2 * w.z; acc[2][3] += a2 * w.w;
      acc[3][0] += a3 * w.x; acc[3][1] += a3 * w.y; acc[3][2] += a3 * w.z; acc[3][3] += a3 * w.w;
    }
    __syncthreads();
  }
  float* dst = &g_part[(size_t)slab * (NB * NH)];
#pragma unroll
  for (int x = 0; x < 4; x++)
#pragma unroll
    for (int yy = 0; yy < 4; yy++)
      dst[(size_t)(m0 + r0 + x) * 64 + c0 + yy] = acc[x][yy];
}

// Parallel ordered compaction body (256 threads).
__device__ __forceinline__ void compact_run(int c, int* wcnt, unsigned* ball) {
  int t = threadIdx.x;
  int w = t >> 5, lane = t & 31;
  int cnt = 0;
#pragma unroll
  for (int s = 0; s < 4; s++) {
    int b = w * 128 + s * 32 + lane;
    bool sel = false;
#pragma unroll
    for (int k = 0; k < KSEL; k++) sel |= (g_idx[b * KSEL + k] == c);
    unsigned m = __ballot_sync(0xffffffffu, sel);
    if (lane == 0) ball[w * 4 + s] = m;
    cnt += __popc(m);
  }
  if (lane == 0) wcnt[w] = cnt;
  __syncthreads();
  int base = 0;
  for (int ww = 0; ww < w; ww++) base += wcnt[ww];
#pragma unroll
  for (int s = 0; s < 4; s++) {
    int b = w * 128 + s * 32 + lane;
    unsigned m = ball[w * 4 + s];
    if ((m >> lane) & 1u) {
      int pos = base + __popc(m & ((1u << lane) - 1u));
      g_nodes[c * NB + pos] = b;
      g_loc[c * NB + b] = pos;
    }
    base += __popc(m);
  }
  if (t == 0) {
    int tot = 0;
    for (int ww = 0; ww < 8; ww++) tot += wcnt[ww];
    g_cnt[c] = tot;
  }
}

// F1: blocks 0-255 gemm feat->slabs0-15; 256-511 head fe3-part->slabs16-31;
//     512-543 compact.
__global__ void k_F1(const float* __restrict__ W0, const float* __restrict__ W1hi) {
  __shared__ float sh[64 * 65 + 64 * 68];
  __shared__ int wcnt[8];
  __shared__ unsigned ball[32];
  int b = blockIdx.x;
  if (b < 512) {
    const float* W = (b < 256) ? W0 : W1hi;
    int slabbase = (b < 256) ? 0 : 16;
    int bb = b & 255;
    gemm_run(g_fe3, 2048, 2048, W, bb & 15, bb >> 4, slabbase + (bb >> 4), 16,
             sh, sh + 64 * 65);
  } else {
    compact_run(b - 512, wcnt, ball);
  }
}

// ---- k_S body: E = exp(S) (mx cancels in w=E/Z); rowsum & Z fused ----------
__device__ __forceinline__ void S_run(int c, int i0, float* pi, float* pj, float* zsh) {
  int n = g_cnt[c];
  if (i0 >= n) return;
  int t = threadIdx.x;  // 256
  for (int e = t; e < 2048; e += 256) {
    int r = e >> 5, k2 = e & 31;
    int gi = i0 + r; if (gi >= n) gi = n - 1;
    pi[r * 33 + k2] = g_p[g_nodes[c * NB + gi] * NCH + k2];
  }
  int ii0 = (t >> 4) * 4;
  int jj0 = (t & 15) * 4;
  float rsum[4] = {0.f, 0.f, 0.f, 0.f};
  float* slab = g_adj + ((size_t)c << 20);
  for (int j0 = 0; j0 < n; j0 += 64) {
    for (int e = t; e < 2048; e += 256) {
      int r = e >> 5, k2 = e & 31;
      int gj = j0 + r; if (gj >= n) gj = n - 1;
      pj[r * 33 + k2] = g_p[g_nodes[c * NB + gj] * NCH + k2];
    }
    __syncthreads();
    float acc[4][4];
#pragma unroll
    for (int x = 0; x < 4; x++)
#pragma unroll
      for (int y = 0; y < 4; y++) acc[x][y] = 0.f;
#pragma unroll 8
    for (int k2 = 0; k2 < 32; k2++) {
      float a[4], bb[4];
#pragma unroll
      for (int x = 0; x < 4; x++) a[x] = pi[(ii0 + x) * 33 + k2];
#pragma unroll
      for (int y = 0; y < 4; y++) bb[y] = pj[(jj0 + y) * 33 + k2];
#pragma unroll
      for (int x = 0; x < 4; x++)
#pragma unroll
        for (int y = 0; y < 4; y++) acc[x][y] += a[x] * bb[y];
    }
#pragma unroll
    for (int x = 0; x < 4; x++) {
      int gi = i0 + ii0 + x;
      if (gi < n) {
        float pic = pi[(ii0 + x) * 33 + c];
#pragma unroll
        for (int y = 0; y < 4; y++) {
          int gj = j0 + jj0 + y;
          if (gj < n) {
            float S = acc[x][y] - pic * pj[(jj0 + y) * 33 + c];
            float E = (gi != gj && S > 0.f) ? __expf(S) : 0.f;
            slab[(size_t)gi * n + gj] = E;
            rsum[x] += E;
          }
        }
      }
    }
    __syncthreads();
  }
  float zloc = 0.f;
#pragma unroll
  for (int x = 0; x < 4; x++) {
#pragma unroll
    for (int o = 8; o; o >>= 1) rsum[x] += __shfl_down_sync(0xffffffffu, rsum[x], o, 16);
    if ((t & 15) == 0) {
      int gi = i0 + ii0 + x;
      if (gi < n) { g_rowsum[c * NB + gi] = rsum[x]; zloc += rsum[x]; }
    }
  }
  if ((t & 15) == 0) zsh[t >> 4] = zloc;
  __syncthreads();
  if (t == 0) {
    float z = 0.f;
    for (int w = 0; w < 16; w++) z += zsh[w];
    atomicAdd(&g_Z[c], z);
  }
}

// F2: blocks 0-63 reduce feat partials -> g_Y; blocks 64-575 k_S.
__global__ void k_F2() {
  __shared__ float pish[64 * 33];
  __shared__ float pjsh[64 * 33];
  __shared__ float zsh[16];
  int b = blockIdx.x;
  if (b < 64) {
    for (int e = b * 256 + threadIdx.x; e < NB * NH; e += 64 * 256) {
      float s = 0.f;
#pragma unroll
      for (int sp = 0; sp < 16; sp++) s += g_part[(size_t)sp * (NB * NH) + e];
      g_Y[e] = s;
    }
  } else {
    int idx = b - 64;
    S_run(idx >> 4, (idx & 15) * 64, pish, pjsh, zsh);
  }
}

// GCN layer 1 with An folded into loader: As = E * di*invZ * dj (diag is 0 in E),
// epilogue adds di^2 * Y[i] + bias, relu, stats1.
__global__ void k_gcn(const float* __restrict__ bias) {
  int c = blockIdx.y;
  int n = g_cnt[c];
  int i0 = blockIdx.x * 64;
  if (i0 >= n) return;
  __shared__ float As[64 * 65];
  __shared__ float Bs[64 * 68];
  __shared__ float djs[NB];
  int t = threadIdx.x;
  float Z = g_Z[c];
  float invZ = (Z > 0.f) ? 1.f / Z : 1.f;
  for (int j = t; j < n; j += 256)
    djs[j] = rsqrtf(1.f + g_rowsum[c * NB + j] * invZ);
  __syncthreads();
  int r0 = (t >> 4) * 4, c0 = (t & 15) * 4;
  float acc[4][4];
#pragma unroll
  for (int x = 0; x < 4; x++)
#pragma unroll
    for (int y = 0; y < 4; y++) acc[x][y] = 0.f;
  const float* slab = g_adj + ((size_t)c << 20);
  for (int j0 = 0; j0 < n; j0 += 64) {
    for (int e = t; e < 4096; e += 256) {
      int r = e >> 6, kk = e & 63;
      int gi = i0 + r, gj = j0 + kk;
      As[r * 65 + kk] = (gi < n && gj < n)
        ? slab[(size_t)gi * n + gj] * (djs[gi] * invZ) * djs[gj] : 0.f;
      int jr = j0 + r;
      Bs[r * 68 + kk] = (jr < n) ? g_Y[g_nodes[c * NB + jr] * 64 + kk] : 0.f;
    }
    __syncthreads();
#pragma unroll 8
    for (int kk = 0; kk < 64; kk++) {
      float a0 = As[r0 * 65 + kk], a1 = As[(r0 + 1) * 65 + kk];
      float a2 = As[(r0 + 2) * 65 + kk], a3 = As[(r0 + 3) * 65 + kk];
      float4 w = *(const float4*)&Bs[kk * 68 + c0];
      acc[0][0] += a0 * w.x; acc[0][1] += a0 * w.y; acc[0][2] += a0 * w.z; acc[0][3] += a0 * w.w;
      acc[1][0] += a1 * w.x; acc[1][1] += a1 * w.y; acc[1][2] += a1 * w.z; acc[1][3] += a1 * w.w;
      acc[2][0] += a2 * w.x; acc[2][1] += a2 * w.y; acc[2][2] += a2 * w.z; acc[2][3] += a2 * w.w;
      acc[3][0] += a3 * w.x; acc[3][1] += a3 * w.y; acc[3][2] += a3 * w.z; acc[3][3] += a3 * w.w;
    }
    __syncthreads();
  }
  float s = 0.f, s2 = 0.f;
#pragma unroll
  for (int x = 0; x < 4; x++) {
    int gi = i0 + r0 + x;
    if (gi < n) {
      float di = djs[gi];
      float d2 = di * di;
      const float* yrow = &g_Y[g_nodes[c * NB + gi] * 64];
#pragma unroll
      for (int y = 0; y < 4; y++) {
        float v = fmaxf(acc[x][y] + d2 * yrow[c0 + y] + bias[c0 + y], 0.f);
        g_X1[((size_t)c * NB + gi) * 64 + c0 + y] = v;
        s += v; s2 += v * v;
      }
    }
  }
#pragma unroll
  for (int o = 16; o; o >>= 1) {
    s  += __shfl_down_sync(0xffffffffu, s, o);
    s2 += __shfl_down_sync(0xffffffffu, s2, o);
  }
  __shared__ float red[16];
  if ((t & 31) == 0) { red[(t >> 5) * 2] = s; red[(t >> 5) * 2 + 1] = s2; }
  __syncthreads();
  if (t == 0) {
    float ts = 0.f, ts2 = 0.f;
    for (int w = 0; w < 8; w++) { ts += red[w * 2]; ts2 += red[w * 2 + 1]; }
    atomicAdd(&g_stats1[c * 2], ts);
    atomicAdd(&g_stats1[c * 2 + 1], ts2);
  }
}

// GCN layer 2 fused: M = An @ LN1(X1) (An folded: As scaled, diag in epilogue),
// then X2 = relu(M @ W2 + bias) in smem epilogue; stats2. Output -> g_T.
__global__ void k_gcn2(const float* __restrict__ W2, const float* __restrict__ bias) {
  int c = blockIdx.y;
  int n = g_cnt[c];
  int i0 = blockIdx.x * 64;
  if (i0 >= n) return;
  __shared__ float As[64 * 65];
  __shared__ float Bs[64 * 68];
  __shared__ float djs[NB];
  int t = threadIdx.x;
  int r0 = (t >> 4) * 4, c0 = (t & 15) * 4;
  float Z = g_Z[c];
  float invZ = (Z > 0.f) ? 1.f / Z : 1.f;
  for (int j = t; j < n; j += 256)
    djs[j] = rsqrtf(1.f + g_rowsum[c * NB + j] * invZ);
  __syncthreads();
  float cntf = (float)n * 64.f;
  float mu = g_stats1[c * 2] / cntf;
  float var = g_stats1[c * 2 + 1] / cntf - mu * mu;
  float rstd = rsqrtf(var + EPS);
  float acc[4][4];
#pragma unroll
  for (int x = 0; x < 4; x++)
#pragma unroll
    for (int y = 0; y < 4; y++) acc[x][y] = 0.f;
  const float* slab = g_adj + ((size_t)c << 20);
  for (int j0 = 0; j0 < n; j0 += 64) {
    for (int e = t; e < 4096; e += 256) {
      int r = e >> 6, kk = e & 63;
      int gi = i0 + r, gj = j0 + kk;
      As[r * 65 + kk] = (gi < n && gj < n)
        ? slab[(size_t)gi * n + gj] * (djs[gi] * invZ) * djs[gj] : 0.f;
      int jr = j0 + r;
      Bs[r * 68 + kk] = (jr < n)
        ? (g_X1[((size_t)c * NB + jr) * 64 + kk] - mu) * rstd : 0.f;
    }
    __syncthreads();
#pragma unroll 8
    for (int kk = 0; kk < 64; kk++) {
      float a0 = As[r0 * 65 + kk], a1 = As[(r0 + 1) * 65 + kk];
      float a2 = As[(r0 + 2) * 65 + kk], a3 = As[(r0 + 3) * 65 + kk];
      float4 w = *(const float4*)&Bs[kk * 68 + c0];
      acc[0][0] += a0 * w.x; acc[0][1] += a0 * w.y; acc[0][2] += a0 * w.z; acc[0][3] += a0 * w.w;
      acc[1][0] += a1 * w.x; acc[1][1] += a1 * w.y; acc[1][2] += a1 * w.z; acc[1][3] += a1 * w.w;
      acc[2][0] += a2 * w.x; acc[2][1] += a2 * w.y; acc[2][2] += a2 * w.z; acc[2][3] += a2 * w.w;
      acc[3][0] += a3 * w.x; acc[3][1] += a3 * w.y; acc[3][2] += a3 * w.z; acc[3][3] += a3 * w.w;
    }
    __syncthreads();
  }
  // add diag: M[i] += di^2 * LN1(X1[i]);  then stage M, W2; X2 = relu(M@W2+bias)
#pragma unroll
  for (int x = 0; x < 4; x++) {
    int gi = i0 + r0 + x;
    if (gi < n) {
      float d2 = djs[gi] * djs[gi];
#pragma unroll
      for (int y = 0; y < 4; y++)
        acc[x][y] += d2 * (g_X1[((size_t)c * NB + gi) * 64 + c0 + y] - mu) * rstd;
    }
#pragma unroll
    for (int y = 0; y < 4; y++)
      As[(r0 + x) * 65 + c0 + y] = acc[x][y];
  }
  for (int e = t; e < 4096; e += 256)
    Bs[(e >> 6) * 68 + (e & 63)] = W2[e];
  __syncthreads();
  float acc2[4][4];
#pragma unroll
  for (int x = 0; x < 4; x++)
#pragma unroll
    for (int y = 0; y < 4; y++) acc2[x][y] = 0.f;
#pragma unroll 8
  for (int kk = 0; kk < 64; kk++) {
    float a0 = As[r0 * 65 + kk], a1 = As[(r0 + 1) * 65 + kk];
    float a2 = As[(r0 + 2) * 65 + kk], a3 = As[(r0 + 3) * 65 + kk];
    float4 w = *(const float4*)&Bs[kk * 68 + c0];
    acc2[0][0] += a0 * w.x; acc2[0][1] += a0 * w.y; acc2[0][2] += a0 * w.z; acc2[0][3] += a0 * w.w;
    acc2[1][0] += a1 * w.x; acc2[1][1] += a1 * w.y; acc2[1][2] += a1 * w.z; acc2[1][3] += a1 * w.w;
    acc2[2][0] += a2 * w.x; acc2[2][1] += a2 * w.y; acc2[2][2] += a2 * w.z; acc2[2][3] += a2 * w.w;
    acc2[3][0] += a3 * w.x; acc2[3][1] += a3 * w.y; acc2[3][2] += a3 * w.z; acc2[3][3] += a3 * w.w;
  }
  float s = 0.f, s2 = 0.f;
#pragma unroll
  for (int x = 0; x < 4; x++) {
    int gi = i0 + r0 + x;
    if (gi < n) {
#pragma unroll
      for (int y = 0; y < 4; y++) {
        float v = fmaxf(acc2[x][y] + bias[c0 + y], 0.f);
        g_T[((size_t)c * NB + gi) * 64 + c0 + y] = v;
        s += v; s2 += v * v;
      }
    }
  }
#pragma unroll
  for (int o = 16; o; o >>= 1) {
    s  += __shfl_down_sync(0xffffffffu, s, o);
    s2 += __shfl_down_sync(0xffffffffu, s2, o);
  }
  __shared__ float red[16];
  if ((t & 31) == 0) { red[(t >> 5) * 2] = s; red[(t >> 5) * 2 + 1] = s2; }
  __syncthreads();
  if (t == 0) {
    float ts = 0.f, ts2 = 0.f;
    for (int w = 0; w < 8; w++) { ts += red[w * 2]; ts2 += red[w * 2 + 1]; }
    atomicAdd(&g_stats2[c * 2], ts);
    atomicAdd(&g_stats2[c * 2 + 1], ts2);
  }
}

// Fused tail: gathered head GEMM (LN2+gather in loader) + hfe slab sum + LN head.
// 64 blocks x 256 threads; block owns 16 rows; group g=t>>4 owns row m0+g,
// lane l=t&15 owns cols l*4..l*4+3.
__global__ void k_headg(const float* __restrict__ W, const float* __restrict__ pb1,
                        const float* __restrict__ pg, const float* __restrict__ pbe,
                        const float* __restrict__ pw2, const float* __restrict__ pb2,
                        float* __restrict__ out) {
  __shared__ float As[16 * 65];
  __shared__ float Ws[64 * 68];
  __shared__ float mu2s[32], rs2s[32];
  int t = threadIdx.x;      // 256
  if (t < 32) {
    float cntf = (float)g_cnt[t] * 64.f;
    float mu = g_stats2[t * 2] / cntf;
    float var = g_stats2[t * 2 + 1] / cntf - mu * mu;
    mu2s[t] = mu;
    rs2s[t] = rsqrtf(var + EPS);
  }
  __syncthreads();
  int m0 = blockIdx.x * 16;
  int g = t >> 4, l = t & 15;
  int c0 = l * 4;
  float acc[4] = {0.f, 0.f, 0.f, 0.f};
  for (int kq = 0; kq < 8; kq++) {
    int k0 = kq * 64;
    for (int e = t; e < 1024; e += 256) {
      int r = e >> 6, kk = e & 63;
      int b = m0 + r;
      int c = g_idx[b * 8 + kq];
      int ip = g_loc[c * NB + b];
      As[r * 65 + kk] = (g_T[((size_t)c * NB + ip) * 64 + kk] - mu2s[c]) * rs2s[c];
    }
    for (int e = t; e < 4096; e += 256) {
      int r = e >> 6, kk = e & 63;
      Ws[r * 68 + kk] = W[(size_t)(k0 + r) * 64 + kk];
    }
    __syncthreads();
#pragma unroll 8
    for (int kk = 0; kk < 64; kk++) {
      float a = As[g * 65 + kk];
      float4 w = *(const float4*)&Ws[kk * 68 + c0];
      acc[0] += a * w.x; acc[1] += a * w.y; acc[2] += a * w.z; acc[3] += a * w.w;
    }
    __syncthreads();
  }
  int gi = m0 + g;
#pragma unroll
  for (int y = 0; y < 4; y++) {
    float sum = acc[y];
#pragma unroll
    for (int sp = 16; sp < 32; sp++)
      sum += g_part[(size_t)sp * (NB * NH) + gi * 64 + c0 + y];
    acc[y] = fmaxf(sum + pb1[c0 + y], 0.f);
  }
  float s = acc[0] + acc[1] + acc[2] + acc[3];
  float s2 = acc[0]*acc[0] + acc[1]*acc[1] + acc[2]*acc[2] + acc[3]*acc[3];
#pragma unroll
  for (int o = 8; o; o >>= 1) {
    s  += __shfl_down_sync(0xffffffffu, s, o, 16);
    s2 += __shfl_down_sync(0xffffffffu, s2, o, 16);
  }
  s  = __shfl_sync(0xffffffffu, s, 0, 16);
  s2 = __shfl_sync(0xffffffffu, s2, 0, 16);
  float mu = s * (1.f / 64.f);
  float var = s2 * (1.f / 64.f) - mu * mu;
  float rstd = rsqrtf(var + EPS);
  float4 ggv = *(const float4*)&pg[c0];
  float4 bev = *(const float4*)&pbe[c0];
  float o0 = 0.f, o1 = 0.f;
#pragma unroll
  for (int y = 0; y < 4; y++) {
    float gv = (y == 0) ? ggv.x : (y == 1) ? ggv.y : (y == 2) ? ggv.z : ggv.w;
    float bv = (y == 0) ? bev.x : (y == 1) ? bev.y : (y == 2) ? bev.z : bev.w;
    float hn = (acc[y] - mu) * rstd * gv + bv;
    o0 += hn * pw2[(c0 + y) * 2];
    o1 += hn * pw2[(c0 + y) * 2 + 1];
  }
#pragma unroll
  for (int o = 8; o; o >>= 1) {
    o0 += __shfl_down_sync(0xffffffffu, o0, o, 16);
    o1 += __shfl_down_sync(0xffffffffu, o1, o, 16);
  }
  if (l == 0) {
    out[gi * 2]     = o0 + pb2[0];
    out[gi * 2 + 1] = o1 + pb2[1];
  }
}

// ---------------------------------------------------------------------------
extern "C" void kernel_launch(void* const* d_in, const int* in_sizes, int n_in,
                              void* d_out, int out_size) {
  const float* num_data = (const float*)d_in[0];
  const int*   cat_data = (const int*)d_in[1];
  const float* num_w    = (const float*)d_in[2];
  const float* num_b    = (const float*)d_in[3];
  const float* cat_emb  = (const float*)d_in[4];
  const float* fi_w1    = (const float*)d_in[5];
  const float* fi_b1    = (const float*)d_in[6];
  const float* fi_g     = (const float*)d_in[7];
  const float* fi_be    = (const float*)d_in[8];
  const float* fi_w2    = (const float*)d_in[9];
  const float* fi_b2    = (const float*)d_in[10];
  const float* gcn1_w   = (const float*)d_in[11];
  const float* gcn1_b   = (const float*)d_in[12];
  const float* gcn2_w   = (const float*)d_in[13];
  const float* gcn2_b   = (const float*)d_in[14];
  const float* pw1      = (const float*)d_in[15];
  const float* pb1      = (const float*)d_in[16];
  const float* pg       = (const float*)d_in[17];
  const float* pbe      = (const float*)d_in[18];
  const float* pw2      = (const float*)d_in[19];
  const float* pb2      = (const float*)d_in[20];

  k_init<<<1, 256>>>();
  k_fe<<<2048, 256>>>(num_data, cat_data, num_w, num_b, cat_emb);
  k_interact<<<1024, 128>>>(fi_w1, fi_b1, fi_g, fi_be, fi_w2, fi_b2);
  k_topk<<<1024, 256>>>();
  k_F1<<<544, 256>>>(gcn1_w, pw1 + 512 * 64);
  k_F2<<<576, 256>>>();
  k_gcn<<<dim3(16, 32), 256>>>(gcn1_b);
  k_gcn2<<<dim3(16, 32), 256>>>(gcn2_w, gcn2_b);
  k_headg<<<64, 256>>>(pw1, pb1, pg, pbe, pw2, pb2, (float*)d_out);
}

// round 15
// speedup vs baseline: 1.0703x; 1.0703x over previous
#include <cuda_runtime.h>
#include <cuda_bf16.h>
#include <math.h>

#define NB   1024
#define NNUM 16
#define NCAT 16
#define NCH  32
#define NH   64
#define NV   100
#define KSEL 8
#define EPS  1e-5f

// ---------------- scratch (static device globals; no allocs) ----------------
__device__ float g_fe3[NB * NCH * NH];            // 8MB
__device__ float g_impraw[NB * NCH];
__device__ float g_p[NB * NCH];
__device__ int   g_idx[NB * KSEL];
__device__ int   g_cnt[NCH];
__device__ int   g_nodes[NCH * NB];
__device__ int   g_loc[NCH * NB];
__device__ float g_Y[NB * NH];
__device__ float g_adj[(size_t)NCH * NB * NB];    // slab: E=exp(S) -> An (in place)
__device__ float g_rowsum[NCH * NB];
__device__ float g_Z[NCH];
__device__ float g_X1[NCH * NB * NH];             // GCN layer-1 output (post-relu)
__device__ float g_T[NCH * NB * NH];              // GCN layer-2 output X2 (post-relu)
__device__ float g_stats1[NCH * 2];
__device__ float g_stats2[NCH * 2];
__device__ float g_sums[8];
__device__ float g_part[32 * NB * NH];            // 8MB split-K partial slabs

// ---------------------------------------------------------------------------
__global__ void k_init() {
  int i = threadIdx.x;
  if (i < 8) g_sums[i] = 0.f;
  if (i < NCH) { g_cnt[i] = 0; g_Z[i] = 0.f; }
  if (i < NCH * 2) { g_stats1[i] = 0.f; g_stats2[i] = 0.f; }
}

__global__ void k_fe(const float* __restrict__ num_data, const int* __restrict__ cat_data,
                     const float* __restrict__ num_w, const float* __restrict__ num_b,
                     const float* __restrict__ cat_emb) {
  int t = threadIdx.x;
  int b = blockIdx.x >> 1;
  int half = blockIdx.x & 1;
  float s = 0.f, s2 = 0.f;
#pragma unroll
  for (int q = 0; q < 4; q++) {
    int off = t + q * 256;
    int ch = off >> 6, h = off & 63;
    float v;
    if (half == 0) {
      v = num_data[b * NNUM + ch] * num_w[ch * NH + h] + num_b[ch * NH + h];
      v = fmaxf(v, 0.f);
    } else {
      v = cat_emb[((size_t)ch * NV + cat_data[b * NCAT + ch]) * NH + h];
    }
    g_fe3[b * 2048 + half * 1024 + off] = v;
    s += v; s2 += v * v;
  }
#pragma unroll
  for (int o = 16; o; o >>= 1) {
    s  += __shfl_down_sync(0xffffffffu, s, o);
    s2 += __shfl_down_sync(0xffffffffu, s2, o);
  }
  __shared__ float red[16];
  if ((t & 31) == 0) { red[(t >> 5) * 2] = s; red[(t >> 5) * 2 + 1] = s2; }
  __syncthreads();
  if (t == 0) {
    float ts = 0.f, ts2 = 0.f;
    for (int w = 0; w < 8; w++) { ts += red[w * 2]; ts2 += red[w * 2 + 1]; }
    atomicAdd(&g_sums[half * 2], ts);
    atomicAdd(&g_sums[half * 2 + 1], ts2);
  }
}

// Register-tiled interact (one row b per block, 128 threads, 4x4 micro-tile).
__global__ void k_interact(const float* __restrict__ w1, const float* __restrict__ b1,
                           const float* __restrict__ gg, const float* __restrict__ be,
                           const float* __restrict__ w2, const float* __restrict__ b2f) {
  int b = blockIdx.x;
  int t = threadIdx.x;             // 128
  int cg = t >> 4, hg = t & 15;
  __shared__ float xsT[64][36];
  __shared__ float w1s[64][68];
  __shared__ float impsh[8][2];
  const float invN = 1.f / 1048576.f;
  float mu0 = g_sums[0] * invN;
  float rs0 = rsqrtf(g_sums[1] * invN - mu0 * mu0 + EPS);
  float mu1 = g_sums[2] * invN;
  float rs1 = rsqrtf(g_sums[3] * invN - mu1 * mu1 + EPS);
  for (int e = t; e < 4096; e += 128) w1s[e >> 6][e & 63] = w1[e];
  for (int e = t; e < 2048; e += 128) {
    int c = e >> 6, i = e & 63;
    float v = g_fe3[b * 2048 + e];
    xsT[i][c] = (c < 16) ? (v - mu0) * rs0 : (v - mu1) * rs1;
  }
  __syncthreads();
  float acc[4][4];
#pragma unroll
  for (int x = 0; x < 4; x++)
#pragma unroll
    for (int y = 0; y < 4; y++) acc[x][y] = 0.f;
#pragma unroll 16
  for (int kk = 0; kk < 64; kk++) {
    float4 a = *(const float4*)&xsT[kk][cg * 4];
    float4 w = *(const float4*)&w1s[kk][hg * 4];
    acc[0][0] += a.x * w.x; acc[0][1] += a.x * w.y; acc[0][2] += a.x * w.z; acc[0][3] += a.x * w.w;
    acc[1][0] += a.y * w.x; acc[1][1] += a.y * w.y; acc[1][2] += a.y * w.z; acc[1][3] += a.y * w.w;
    acc[2][0] += a.z * w.x; acc[2][1] += a.z * w.y; acc[2][2] += a.z * w.z; acc[2][3] += a.z * w.w;
    acc[3][0] += a.w * w.x; acc[3][1] += a.w * w.y; acc[3][2] += a.w * w.z; acc[3][3] += a.w * w.w;
  }
  int h0 = hg * 4;
  float4 b1v = *(const float4*)&b1[h0];
  float4 ggv = *(const float4*)&gg[h0];
  float4 bev = *(const float4*)&be[h0];
  float4 w2v = *(const float4*)&w2[h0];
  float b2v = b2f[0];
  float simp = 0.f, simp2 = 0.f;
#pragma unroll
  for (int x = 0; x < 4; x++) {
    float v0 = fmaxf(acc[x][0] + b1v.x, 0.f);
    float v1 = fmaxf(acc[x][1] + b1v.y, 0.f);
    float v2 = fmaxf(acc[x][2] + b1v.z, 0.f);
    float v3 = fmaxf(acc[x][3] + b1v.w, 0.f);
    float s  = v0 + v1 + v2 + v3;
    float s2 = v0 * v0 + v1 * v1 + v2 * v2 + v3 * v3;
#pragma unroll
    for (int o = 8; o; o >>= 1) {
      s  += __shfl_down_sync(0xffffffffu, s, o, 16);
      s2 += __shfl_down_sync(0xffffffffu, s2, o, 16);
    }
    s  = __shfl_sync(0xffffffffu, s, 0, 16);
    s2 = __shfl_sync(0xffffffffu, s2, 0, 16);
    float mu = s * (1.f / 64.f);
    float var = s2 * (1.f / 64.f) - mu * mu;
    float rstd = rsqrtf(var + EPS);
    float pp = ((v0 - mu) * rstd * ggv.x + bev.x) * w2v.x
             + ((v1 - mu) * rstd * ggv.y + bev.y) * w2v.y
             + ((v2 - mu) * rstd * ggv.z + bev.z) * w2v.z
             + ((v3 - mu) * rstd * ggv.w + bev.w) * w2v.w;
#pragma unroll
    for (int o = 8; o; o >>= 1) pp += __shfl_down_sync(0xffffffffu, pp, o, 16);
    if (hg == 0) {
      float val = pp + b2v;
      g_impraw[b * 32 + cg * 4 + x] = val;
      simp += val; simp2 += val * val;
    }
  }
  if (hg == 0) { impsh[cg][0] = simp; impsh[cg][1] = simp2; }
  __syncthreads();
  if (t == 0) {
    float a = 0.f, bsq = 0.f;
    for (int w = 0; w < 8; w++) { a += impsh[w][0]; bsq += impsh[w][1]; }
    atomicAdd(&g_sums[4], a);
    atomicAdd(&g_sums[5], bsq);
  }
}

// Merged: warp0 does top-8 + softmax p + sorted idx; all 256 threads scale fe3.
__global__ void k_topk() {
  int b = blockIdx.x;
  int t = threadIdx.x;  // 256
  __shared__ float imps[32];
  const float inv = 1.f / (NB * NCH);
  float mui = g_sums[4] * inv;
  float rsi = rsqrtf(g_sums[5] * inv - mui * mui + EPS);
  if (t < 32) {
    float imp = (g_impraw[b * 32 + t] - mui) * rsi;
    imps[t] = imp;
    float v = imp;
    float mx0 = 0.f;
#pragma unroll
    for (int k = 0; k < KSEL; k++) {
      float m = v; int mi = t;
#pragma unroll
      for (int o = 16; o; o >>= 1) {
        float om = __shfl_down_sync(0xffffffffu, m, o);
        int   oi = __shfl_down_sync(0xffffffffu, mi, o);
        if (om > m) { m = om; mi = oi; }
      }
      m  = __shfl_sync(0xffffffffu, m, 0);
      mi = __shfl_sync(0xffffffffu, mi, 0);
      if (k == 0) mx0 = m;
      if (t == mi) v = -1e30f;
    }
    bool chosen = (v == -1e30f);
    float e = chosen ? __expf(imp - mx0) : 0.f;
    float es = e;
#pragma unroll
    for (int o = 16; o; o >>= 1) es += __shfl_xor_sync(0xffffffffu, es, o);
    g_p[b * 32 + t] = e / es;
    unsigned bal = __ballot_sync(0xffffffffu, chosen);
    if (chosen) {
      int rank = __popc(bal & ((1u << t) - 1u));
      g_idx[b * KSEL + rank] = t;   // ascending by construction
    }
  }
  __syncthreads();
  const float invN = 1.f / 1048576.f;
  float mu0 = g_sums[0] * invN;
  float rs0 = rsqrtf(g_sums[1] * invN - mu0 * mu0 + EPS);
  float mu1 = g_sums[2] * invN;
  float rs1 = rsqrtf(g_sums[3] * invN - mu1 * mu1 + EPS);
  float4* p4 = (float4*)&g_fe3[b * 2048];
#pragma unroll
  for (int k = 0; k < 2; k++) {
    int q4 = t + k * 256;                  // 0..511
    float impv = imps[q4 >> 4];
    float mu = (q4 < 256) ? mu0 : mu1;
    float rs = (q4 < 256) ? rs0 : rs1;
    float4 x = p4[q4];
    x.x = (x.x - mu) * rs * impv;
    x.y = (x.y - mu) * rs * impv;
    x.z = (x.z - mu) * rs * impv;
    x.w = (x.w - mu) * rs * impv;
    p4[q4] = x;
  }
}

// ---------------- shared GEMM body on raw shared pointers -------------------
__device__ __forceinline__ void gemm_run(const float* __restrict__ A, int lda, int Kd,
                                         const float* __restrict__ W,
                                         int m, int y, int slab, int stride,
                                         float* __restrict__ As, float* __restrict__ Ws) {
  int t = threadIdx.x;      // 256
  int m0 = m * 64;
  int r0 = (t >> 4) * 4;
  int c0 = (t & 15) * 4;
  float acc[4][4];
#pragma unroll
  for (int x = 0; x < 4; x++)
#pragma unroll
    for (int yy = 0; yy < 4; yy++) acc[x][yy] = 0.f;
  for (int ch = y; ch * 64 < Kd; ch += stride) {
    int k0 = ch * 64;
    for (int e = t; e < 4096; e += 256) {
      int r = e >> 6, kk = e & 63;
      As[r * 65 + kk] = A[(size_t)(m0 + r) * lda + k0 + kk];
      Ws[r * 68 + kk] = W[(size_t)(k0 + r) * 64 + kk];
    }
    __syncthreads();
#pragma unroll 8
    for (int kk = 0; kk < 64; kk++) {
      float a0 = As[r0 * 65 + kk], a1 = As[(r0 + 1) * 65 + kk];
      float a2 = As[(r0 + 2) * 65 + kk], a3 = As[(r0 + 3) * 65 + kk];
      float4 w = *(const float4*)&Ws[kk * 68 + c0];
      acc[0][0] += a0 * w.x; acc[0][1] += a0 * w.y; acc[0][2] += a0 * w.z; acc[0][3] += a0 * w.w;
      acc[1][0] += a1 * w.x; acc[1][1] += a1 * w.y; acc[1][2] += a1 * w.z; acc[1][3] += a1 * w.w;
      acc[2][0] += a2 * w.x; acc[2][1] += a2 * w.y; acc[2][2] += a2 * w.z; acc[2][3] += a2 * w.w;
      acc[3][0] += a3 * w.x; acc[3][1] += a3 * w.y; acc[3][2] += a3 * w.z; acc[3][3] += a3 * w.w;
    }
    __syncthreads();
  }
  float* dst = &g_part[(size_t)slab * (NB * NH)];
#pragma unroll
  for (int x = 0; x < 4; x++)
#pragma unroll
    for (int yy = 0; yy < 4; yy++)
      dst[(size_t)(m0 + r0 + x) * 64 + c0 + yy] = acc[x][yy];
}

// Parallel ordered compaction body (256 threads).
__device__ __forceinline__ void compact_run(int c, int* wcnt, unsigned* ball) {
  int t = threadIdx.x;
  int w = t >> 5, lane = t & 31;
  int cnt = 0;
#pragma unroll
  for (int s = 0; s < 4; s++) {
    int b = w * 128 + s * 32 + lane;
    bool sel = false;
#pragma unroll
    for (int k = 0; k < KSEL; k++) sel |= (g_idx[b * KSEL + k] == c);
    unsigned m = __ballot_sync(0xffffffffu, sel);
    if (lane == 0) ball[w * 4 + s] = m;
    cnt += __popc(m);
  }
  if (lane == 0) wcnt[w] = cnt;
  __syncthreads();
  int base = 0;
  for (int ww = 0; ww < w; ww++) base += wcnt[ww];
#pragma unroll
  for (int s = 0; s < 4; s++) {
    int b = w * 128 + s * 32 + lane;
    unsigned m = ball[w * 4 + s];
    if ((m >> lane) & 1u) {
      int pos = base + __popc(m & ((1u << lane) - 1u));
      g_nodes[c * NB + pos] = b;
      g_loc[c * NB + b] = pos;
    }
    base += __popc(m);
  }
  if (t == 0) {
    int tot = 0;
    for (int ww = 0; ww < 8; ww++) tot += wcnt[ww];
    g_cnt[c] = tot;
  }
}

// F1: blocks 0-255 gemm feat->slabs0-15; 256-511 head fe3-part->slabs16-31;
//     512-543 compact.
__global__ void k_F1(const float* __restrict__ W0, const float* __restrict__ W1hi) {
  __shared__ float sh[64 * 65 + 64 * 68];
  __shared__ int wcnt[8];
  __shared__ unsigned ball[32];
  int b = blockIdx.x;
  if (b < 512) {
    const float* W = (b < 256) ? W0 : W1hi;
    int slabbase = (b < 256) ? 0 : 16;
    int bb = b & 255;
    gemm_run(g_fe3, 2048, 2048, W, bb & 15, bb >> 4, slabbase + (bb >> 4), 16,
             sh, sh + 64 * 65);
  } else {
    compact_run(b - 512, wcnt, ball);
  }
}

// ---- k_S body: E = exp(S) (mx cancels in w=E/Z); rowsum & Z fused ----------
__device__ __forceinline__ void S_run(int c, int i0, float* pi, float* pj, float* zsh) {
  int n = g_cnt[c];
  if (i0 >= n) return;
  int t = threadIdx.x;  // 256
  for (int e = t; e < 2048; e += 256) {
    int r = e >> 5, k2 = e & 31;
    int gi = i0 + r; if (gi >= n) gi = n - 1;
    pi[r * 33 + k2] = g_p[g_nodes[c * NB + gi] * NCH + k2];
  }
  int ii0 = (t >> 4) * 4;
  int jj0 = (t & 15) * 4;
  float rsum[4] = {0.f, 0.f, 0.f, 0.f};
  float* slab = g_adj + ((size_t)c << 20);
  for (int j0 = 0; j0 < n; j0 += 64) {
    for (int e = t; e < 2048; e += 256) {
      int r = e >> 5, k2 = e & 31;
      int gj = j0 + r; if (gj >= n) gj = n - 1;
      pj[r * 33 + k2] = g_p[g_nodes[c * NB + gj] * NCH + k2];
    }
    __syncthreads();
    float acc[4][4];
#pragma unroll
    for (int x = 0; x < 4; x++)
#pragma unroll
      for (int y = 0; y < 4; y++) acc[x][y] = 0.f;
#pragma unroll 8
    for (int k2 = 0; k2 < 32; k2++) {
      float a[4], bb[4];
#pragma unroll
      for (int x = 0; x < 4; x++) a[x] = pi[(ii0 + x) * 33 + k2];
#pragma unroll
      for (int y = 0; y < 4; y++) bb[y] = pj[(jj0 + y) * 33 + k2];
#pragma unroll
      for (int x = 0; x < 4; x++)
#pragma unroll
        for (int y = 0; y < 4; y++) acc[x][y] += a[x] * bb[y];
    }
#pragma unroll
    for (int x = 0; x < 4; x++) {
      int gi = i0 + ii0 + x;
      if (gi < n) {
        float pic = pi[(ii0 + x) * 33 + c];
#pragma unroll
        for (int y = 0; y < 4; y++) {
          int gj = j0 + jj0 + y;
          if (gj < n) {
            float S = acc[x][y] - pic * pj[(jj0 + y) * 33 + c];
            float E = (gi != gj && S > 0.f) ? __expf(S) : 0.f;
            slab[(size_t)gi * n + gj] = E;
            rsum[x] += E;
          }
        }
      }
    }
    __syncthreads();
  }
  float zloc = 0.f;
#pragma unroll
  for (int x = 0; x < 4; x++) {
#pragma unroll
    for (int o = 8; o; o >>= 1) rsum[x] += __shfl_down_sync(0xffffffffu, rsum[x], o, 16);
    if ((t & 15) == 0) {
      int gi = i0 + ii0 + x;
      if (gi < n) { g_rowsum[c * NB + gi] = rsum[x]; zloc += rsum[x]; }
    }
  }
  if ((t & 15) == 0) zsh[t >> 4] = zloc;
  __syncthreads();
  if (t == 0) {
    float z = 0.f;
    for (int w = 0; w < 16; w++) z += zsh[w];
    atomicAdd(&g_Z[c], z);
  }
}

// F2: blocks 0-63 reduce feat partials -> g_Y; blocks 64-575 k_S.
__global__ void k_F2() {
  __shared__ float pish[64 * 33];
  __shared__ float pjsh[64 * 33];
  __shared__ float zsh[16];
  int b = blockIdx.x;
  if (b < 64) {
    for (int e = b * 256 + threadIdx.x; e < NB * NH; e += 64 * 256) {
      float s = 0.f;
#pragma unroll
      for (int sp = 0; sp < 16; sp++) s += g_part[(size_t)sp * (NB * NH) + e];
      g_Y[e] = s;
    }
  } else {
    int idx = b - 64;
    S_run(idx >> 4, (idx & 15) * 64, pish, pjsh, zsh);
  }
}

// An = E*invZ*di*dj (+ diag di^2) streamed in place; dinv computed on the fly.
// High-parallelism grid: (1024, 32) x 128 threads.
__global__ void k_An() {
  int c = blockIdx.y;
  int n = g_cnt[c];
  int i = blockIdx.x;
  if (i >= n) return;
  float Z = g_Z[c];
  float invZ = (Z > 0.f) ? 1.f / Z : 1.f;
  float di = rsqrtf(1.f + g_rowsum[c * NB + i] * invZ);
  float fi = di * invZ;
  float* row = g_adj + ((size_t)c << 20) + (size_t)i * n;
  for (int j = threadIdx.x; j < n; j += 128) {
    float dj = rsqrtf(1.f + g_rowsum[c * NB + j] * invZ);
    float v = row[j] * fi * dj;
    if (j == i) v += di * di;
    row[j] = v;
  }
}

// GCN layer 1: X1[i,h] = relu(sum_j An[i,j]*Y[nodes[j],h] + bias[h]); stats1.
__global__ void k_gcn(const float* __restrict__ bias) {
  int c = blockIdx.y;
  int n = g_cnt[c];
  int i0 = blockIdx.x * 64;
  if (i0 >= n) return;
  __shared__ float As[64][65];
  __shared__ float Bs[64][68];
  int t = threadIdx.x;
  int r0 = (t >> 4) * 4, c0 = (t & 15) * 4;
  float acc[4][4];
#pragma unroll
  for (int x = 0; x < 4; x++)
#pragma unroll
    for (int y = 0; y < 4; y++) acc[x][y] = 0.f;
  const float* slab = g_adj + ((size_t)c << 20);
  for (int j0 = 0; j0 < n; j0 += 64) {
    for (int e = t; e < 4096; e += 256) {
      int r = e >> 6, kk = e & 63;
      int gi = i0 + r, gj = j0 + kk;
      As[r][kk] = (gi < n && gj < n) ? slab[(size_t)gi * n + gj] : 0.f;
      int jr = j0 + r;
      Bs[r][kk] = (jr < n) ? g_Y[g_nodes[c * NB + jr] * 64 + kk] : 0.f;
    }
    __syncthreads();
#pragma unroll 8
    for (int kk = 0; kk < 64; kk++) {
      float a0 = As[r0][kk], a1 = As[r0 + 1][kk], a2 = As[r0 + 2][kk], a3 = As[r0 + 3][kk];
      float4 w = *(const float4*)&Bs[kk][c0];
      acc[0][0] += a0 * w.x; acc[0][1] += a0 * w.y; acc[0][2] += a0 * w.z; acc[0][3] += a0 * w.w;
      acc[1][0] += a1 * w.x; acc[1][1] += a1 * w.y; acc[1][2] += a1 * w.z; acc[1][3] += a1 * w.w;
      acc[2][0] += a2 * w.x; acc[2][1] += a2 * w.y; acc[2][2] += a2 * w.z; acc[2][3] += a2 * w.w;
      acc[3][0] += a3 * w.x; acc[3][1] += a3 * w.y; acc[3][2] += a3 * w.z; acc[3][3] += a3 * w.w;
    }
    __syncthreads();
  }
  float s = 0.f, s2 = 0.f;
#pragma unroll
  for (int x = 0; x < 4; x++) {
    int gi = i0 + r0 + x;
    if (gi < n) {
#pragma unroll
      for (int y = 0; y < 4; y++) {
        float v = fmaxf(acc[x][y] + bias[c0 + y], 0.f);
        g_X1[((size_t)c * NB + gi) * 64 + c0 + y] = v;
        s += v; s2 += v * v;
      }
    }
  }
#pragma unroll
  for (int o = 16; o; o >>= 1) {
    s  += __shfl_down_sync(0xffffffffu, s, o);
    s2 += __shfl_down_sync(0xffffffffu, s2, o);
  }
  __shared__ float red[16];
  if ((t & 31) == 0) { red[(t >> 5) * 2] = s; red[(t >> 5) * 2 + 1] = s2; }
  __syncthreads();
  if (t == 0) {
    float ts = 0.f, ts2 = 0.f;
    for (int w = 0; w < 8; w++) { ts += red[w * 2]; ts2 += red[w * 2 + 1]; }
    atomicAdd(&g_stats1[c * 2], ts);
    atomicAdd(&g_stats1[c * 2 + 1], ts2);
  }
}

// GCN layer 2 fused: M = An @ LN1(X1)  (LN1 elementwise in loader),
// then X2 = relu(M @ W2 + bias) in smem epilogue; stats2. Output -> g_T.
__global__ void k_gcn2(const float* __restrict__ W2, const float* __restrict__ bias) {
  int c = blockIdx.y;
  int n = g_cnt[c];
  int i0 = blockIdx.x * 64;
  if (i0 >= n) return;
  __shared__ float As[64 * 65];
  __shared__ float Bs[64 * 68];
  int t = threadIdx.x;
  int r0 = (t >> 4) * 4, c0 = (t & 15) * 4;
  float cntf = (float)n * 64.f;
  float mu = g_stats1[c * 2] / cntf;
  float var = g_stats1[c * 2 + 1] / cntf - mu * mu;
  float rstd = rsqrtf(var + EPS);
  float acc[4][4];
#pragma unroll
  for (int x = 0; x < 4; x++)
#pragma unroll
    for (int y = 0; y < 4; y++) acc[x][y] = 0.f;
  const float* slab = g_adj + ((size_t)c << 20);
  for (int j0 = 0; j0 < n; j0 += 64) {
    for (int e = t; e < 4096; e += 256) {
      int r = e >> 6, kk = e & 63;
      int gi = i0 + r, gj = j0 + kk;
      As[r * 65 + kk] = (gi < n && gj < n) ? slab[(size_t)gi * n + gj] : 0.f;
      int jr = j0 + r;
      Bs[r * 68 + kk] = (jr < n)
        ? (g_X1[((size_t)c * NB + jr) * 64 + kk] - mu) * rstd : 0.f;
    }
    __syncthreads();
#pragma unroll 8
    for (int kk = 0; kk < 64; kk++) {
      float a0 = As[r0 * 65 + kk], a1 = As[(r0 + 1) * 65 + kk];
      float a2 = As[(r0 + 2) * 65 + kk], a3 = As[(r0 + 3) * 65 + kk];
      float4 w = *(const float4*)&Bs[kk * 68 + c0];
      acc[0][0] += a0 * w.x; acc[0][1] += a0 * w.y; acc[0][2] += a0 * w.z; acc[0][3] += a0 * w.w;
      acc[1][0] += a1 * w.x; acc[1][1] += a1 * w.y; acc[1][2] += a1 * w.z; acc[1][3] += a1 * w.w;
      acc[2][0] += a2 * w.x; acc[2][1] += a2 * w.y; acc[2][2] += a2 * w.z; acc[2][3] += a2 * w.w;
      acc[3][0] += a3 * w.x; acc[3][1] += a3 * w.y; acc[3][2] += a3 * w.z; acc[3][3] += a3 * w.w;
    }
    __syncthreads();
  }
  // epilogue: stage M in As, W2 in Bs, compute X2 = relu(M@W2 + bias)
#pragma unroll
  for (int x = 0; x < 4; x++)
#pragma unroll
    for (int y = 0; y < 4; y++)
      As[(r0 + x) * 65 + c0 + y] = acc[x][y];
  for (int e = t; e < 4096; e += 256)
    Bs[(e >> 6) * 68 + (e & 63)] = W2[e];
  __syncthreads();
  float acc2[4][4];
#pragma unroll
  for (int x = 0; x < 4; x++)
#pragma unroll
    for (int y = 0; y < 4; y++) acc2[x][y] = 0.f;
#pragma unroll 8
  for (int kk = 0; kk < 64; kk++) {
    float a0 = As[r0 * 65 + kk], a1 = As[(r0 + 1) * 65 + kk];
    float a2 = As[(r0 + 2) * 65 + kk], a3 = As[(r0 + 3) * 65 + kk];
    float4 w = *(const float4*)&Bs[kk * 68 + c0];
    acc2[0][0] += a0 * w.x; acc2[0][1] += a0 * w.y; acc2[0][2] += a0 * w.z; acc2[0][3] += a0 * w.w;
    acc2[1][0] += a1 * w.x; acc2[1][1] += a1 * w.y; acc2[1][2] += a1 * w.z; acc2[1][3] += a1 * w.w;
    acc2[2][0] += a2 * w.x; acc2[2][1] += a2 * w.y; acc2[2][2] += a2 * w.z; acc2[2][3] += a2 * w.w;
    acc2[3][0] += a3 * w.x; acc2[3][1] += a3 * w.y; acc2[3][2] += a3 * w.z; acc2[3][3] += a3 * w.w;
  }
  float s = 0.f, s2 = 0.f;
#pragma unroll
  for (int x = 0; x < 4; x++) {
    int gi = i0 + r0 + x;
    if (gi < n) {
#pragma unroll
      for (int y = 0; y < 4; y++) {
        float v = fmaxf(acc2[x][y] + bias[c0 + y], 0.f);
        g_T[((size_t)c * NB + gi) * 64 + c0 + y] = v;
        s += v; s2 += v * v;
      }
    }
  }
#pragma unroll
  for (int o = 16; o; o >>= 1) {
    s  += __shfl_down_sync(0xffffffffu, s, o);
    s2 += __shfl_down_sync(0xffffffffu, s2, o);
  }
  __shared__ float red[16];
  if ((t & 31) == 0) { red[(t >> 5) * 2] = s; red[(t >> 5) * 2 + 1] = s2; }
  __syncthreads();
  if (t == 0) {
    float ts = 0.f, ts2 = 0.f;
    for (int w = 0; w < 8; w++) { ts += red[w * 2]; ts2 += red[w * 2 + 1]; }
    atomicAdd(&g_stats2[c * 2], ts);
    atomicAdd(&g_stats2[c * 2 + 1], ts2);
  }
}

// gathered-part head GEMM with LN2+gather fused in the A loader. slabs 0-7.
__global__ void k_gemm_gath(const float* __restrict__ W) {
  __shared__ float As[64 * 65];
  __shared__ float Ws[64 * 68];
  __shared__ float mu2s[32], rs2s[32];
  int t = threadIdx.x;      // 256
  if (t < 32) {
    float cntf = (float)g_cnt[t] * 64.f;
    float mu = g_stats2[t * 2] / cntf;
    float var = g_stats2[t * 2 + 1] / cntf - mu * mu;
    mu2s[t] = mu;
    rs2s[t] = rsqrtf(var + EPS);
  }
  __syncthreads();
  int m0 = blockIdx.x * 64;
  int k0 = blockIdx.y * 64;   // one chunk per block (Kd=512, 8 slabs)
  int kq = k0 >> 6;           // which of the 8 gathered channel slots
  int r0 = (t >> 4) * 4;
  int c0 = (t & 15) * 4;
  float acc[4][4];
#pragma unroll
  for (int x = 0; x < 4; x++)
#pragma unroll
    for (int y = 0; y < 4; y++) acc[x][y] = 0.f;
  for (int e = t; e < 4096; e += 256) {
    int r = e >> 6, kk = e & 63;
    int b = m0 + r;
    int c = g_idx[b * 8 + kq];
    int ip = g_loc[c * NB + b];
    As[r * 65 + kk] = (g_T[((size_t)c * NB + ip) * 64 + kk] - mu2s[c]) * rs2s[c];
    Ws[r * 68 + kk] = W[(size_t)(k0 + r) * 64 + kk];
  }
  __syncthreads();
#pragma unroll 8
  for (int kk = 0; kk < 64; kk++) {
    float a0 = As[r0 * 65 + kk], a1 = As[(r0 + 1) * 65 + kk];
    float a2 = As[(r0 + 2) * 65 + kk], a3 = As[(r0 + 3) * 65 + kk];
    float4 w = *(const float4*)&Ws[kk * 68 + c0];
    acc[0][0] += a0 * w.x; acc[0][1] += a0 * w.y; acc[0][2] += a0 * w.z; acc[0][3] += a0 * w.w;
    acc[1][0] += a1 * w.x; acc[1][1] += a1 * w.y; acc[1][2] += a1 * w.z; acc[1][3] += a1 * w.w;
    acc[2][0] += a2 * w.x; acc[2][1] += a2 * w.y; acc[2][2] += a2 * w.z; acc[2][3] += a2 * w.w;
    acc[3][0] += a3 * w.x; acc[3][1] += a3 * w.y; acc[3][2] += a3 * w.z; acc[3][3] += a3 * w.w;
  }
  float* dst = &g_part[(size_t)blockIdx.y * (NB * NH)];
#pragma unroll
  for (int x = 0; x < 4; x++)
#pragma unroll
    for (int y = 0; y < 4; y++)
      dst[(size_t)(m0 + r0 + x) * 64 + c0 + y] = acc[x][y];
}

// head: sum hfe slabs (16-31) + gath slabs (0-7), then LN head.
__global__ void k_head(const float* __restrict__ pb1, const float* __restrict__ pg,
                       const float* __restrict__ pbe, const float* __restrict__ pw2,
                       const float* __restrict__ pb2, float* __restrict__ out) {
  int b = blockIdx.x, t = threadIdx.x;  // 64
  int e = b * 64 + t;
  float acc = 0.f;
#pragma unroll
  for (int sp = 16; sp < 32; sp++) acc += g_part[(size_t)sp * (NB * NH) + e];
#pragma unroll
  for (int sp = 0; sp < 8; sp++) acc += g_part[(size_t)sp * (NB * NH) + e];
  float v = fmaxf(acc + pb1[t], 0.f);
  float s = v, s2 = v * v;
#pragma unroll
  for (int o = 16; o; o >>= 1) {
    s  += __shfl_down_sync(0xffffffffu, s, o);
    s2 += __shfl_down_sync(0xffffffffu, s2, o);
  }
  __shared__ float red[4];
  __shared__ float red2[4];
  if ((t & 31) == 0) { red[(t >> 5) * 2] = s; red[(t >> 5) * 2 + 1] = s2; }
  __syncthreads();
  float mu = (red[0] + red[2]) * (1.f / 64.f);
  float var = (red[1] + red[3]) * (1.f / 64.f) - mu * mu;
  float rstd = rsqrtf(var + EPS);
  float hn = (v - mu) * rstd * pg[t] + pbe[t];
  float o0 = hn * pw2[t * 2];
  float o1 = hn * pw2[t * 2 + 1];
#pragma unroll
  for (int o = 16; o; o >>= 1) {
    o0 += __shfl_down_sync(0xffffffffu, o0, o);
    o1 += __shfl_down_sync(0xffffffffu, o1, o);
  }
  if ((t & 31) == 0) { red2[(t >> 5) * 2] = o0; red2[(t >> 5) * 2 + 1] = o1; }
  __syncthreads();
  if (t == 0) {
    out[b * 2]     = red2[0] + red2[2] + pb2[0];
    out[b * 2 + 1] = red2[1] + red2[3] + pb2[1];
  }
}

// ---------------------------------------------------------------------------
extern "C" void kernel_launch(void* const* d_in, const int* in_sizes, int n_in,
                              void* d_out, int out_size) {
  const float* num_data = (const float*)d_in[0];
  const int*   cat_data = (const int*)d_in[1];
  const float* num_w    = (const float*)d_in[2];
  const float* num_b    = (const float*)d_in[3];
  const float* cat_emb  = (const float*)d_in[4];
  const float* fi_w1    = (const float*)d_in[5];
  const float* fi_b1    = (const float*)d_in[6];
  const float* fi_g     = (const float*)d_in[7];
  const float* fi_be    = (const float*)d_in[8];
  const float* fi_w2    = (const float*)d_in[9];
  const float* fi_b2    = (const float*)d_in[10];
  const float* gcn1_w   = (const float*)d_in[11];
  const float* gcn1_b   = (const float*)d_in[12];
  const float* gcn2_w   = (const float*)d_in[13];
  const float* gcn2_b   = (const float*)d_in[14];
  const float* pw1      = (const float*)d_in[15];
  const float* pb1      = (const float*)d_in[16];
  const float* pg       = (const float*)d_in[17];
  const float* pbe      = (const float*)d_in[18];
  const float* pw2      = (const float*)d_in[19];
  const float* pb2      = (const float*)d_in[20];

  k_init<<<1, 256>>>();
  k_fe<<<2048, 256>>>(num_data, cat_data, num_w, num_b, cat_emb);
  k_interact<<<1024, 128>>>(fi_w1, fi_b1, fi_g, fi_be, fi_w2, fi_b2);
  k_topk<<<1024, 256>>>();
  k_F1<<<544, 256>>>(gcn1_w, pw1 + 512 * 64);
  k_F2<<<576, 256>>>();
  k_An<<<dim3(1024, 32), 128>>>();
  k_gcn<<<dim3(16, 32), 256>>>(gcn1_b);
  k_gcn2<<<dim3(16, 32), 256>>>(gcn2_w, gcn2_b);
  k_gemm_gath<<<dim3(16, 8), 256>>>(pw1);
  k_head<<<1024, 64>>>(pb1, pg, pbe, pw2, pb2, (float*)d_out);
}

// round 16
// speedup vs baseline: 1.1689x; 1.0921x over previous
#include <cuda_runtime.h>
#include <cuda_bf16.h>
#include <math.h>

#define NB   1024
#define NNUM 16
#define NCAT 16
#define NCH  32
#define NH   64
#define NV   100
#define KSEL 8
#define EPS  1e-5f

// ---------------- scratch (static device globals; no allocs) ----------------
__device__ float g_fe3[NB * NCH * NH];            // 8MB
__device__ float g_impraw[NB * NCH];
__device__ float g_p[NB * NCH];
__device__ int   g_idx[NB * KSEL];
__device__ int   g_cnt[NCH];
__device__ int   g_nodes[NCH * NB];
__device__ int   g_loc[NCH * NB];
__device__ float g_Y[NB * NH];
__device__ float g_adj[(size_t)NCH * NB * NB];    // slab: E=exp(S) -> An (in place)
__device__ float g_rowsum[NCH * NB];
__device__ float g_Z[NCH];
__device__ float g_X1[NCH * NB * NH];             // GCN layer-1 output (post-relu)
__device__ float g_T[NCH * NB * NH];              // GCN layer-2 output X2 (post-relu)
__device__ float g_stats1[NCH * 2];
__device__ float g_stats2[NCH * 2];
__device__ float g_sums[8];
__device__ float g_part[32 * NB * NH];            // 8MB split-K partial slabs

// ---------------------------------------------------------------------------
__global__ void k_init() {
  int gt = blockIdx.x * 256 + threadIdx.x;
  if (gt < 8) g_sums[gt] = 0.f;
  if (gt < NCH) { g_cnt[gt] = 0; g_Z[gt] = 0.f; }
  if (gt < NCH * 2) { g_stats1[gt] = 0.f; g_stats2[gt] = 0.f; }
  if (gt < NCH * NB) g_rowsum[gt] = 0.f;
}

__global__ void k_fe(const float* __restrict__ num_data, const int* __restrict__ cat_data,
                     const float* __restrict__ num_w, const float* __restrict__ num_b,
                     const float* __restrict__ cat_emb) {
  int t = threadIdx.x;
  int b = blockIdx.x >> 1;
  int half = blockIdx.x & 1;
  float s = 0.f, s2 = 0.f;
#pragma unroll
  for (int q = 0; q < 4; q++) {
    int off = t + q * 256;
    int ch = off >> 6, h = off & 63;
    float v;
    if (half == 0) {
      v = num_data[b * NNUM + ch] * num_w[ch * NH + h] + num_b[ch * NH + h];
      v = fmaxf(v, 0.f);
    } else {
      v = cat_emb[((size_t)ch * NV + cat_data[b * NCAT + ch]) * NH + h];
    }
    g_fe3[b * 2048 + half * 1024 + off] = v;
    s += v; s2 += v * v;
  }
#pragma unroll
  for (int o = 16; o; o >>= 1) {
    s  += __shfl_down_sync(0xffffffffu, s, o);
    s2 += __shfl_down_sync(0xffffffffu, s2, o);
  }
  __shared__ float red[16];
  if ((t & 31) == 0) { red[(t >> 5) * 2] = s; red[(t >> 5) * 2 + 1] = s2; }
  __syncthreads();
  if (t == 0) {
    float ts = 0.f, ts2 = 0.f;
    for (int w = 0; w < 8; w++) { ts += red[w * 2]; ts2 += red[w * 2 + 1]; }
    atomicAdd(&g_sums[half * 2], ts);
    atomicAdd(&g_sums[half * 2 + 1], ts2);
  }
}

// Register-tiled interact (one row b per block, 128 threads, 4x4 micro-tile).
__global__ void k_interact(const float* __restrict__ w1, const float* __restrict__ b1,
                           const float* __restrict__ gg, const float* __restrict__ be,
                           const float* __restrict__ w2, const float* __restrict__ b2f) {
  int b = blockIdx.x;
  int t = threadIdx.x;             // 128
  int cg = t >> 4, hg = t & 15;
  __shared__ float xsT[64][36];
  __shared__ float w1s[64][68];
  __shared__ float impsh[8][2];
  const float invN = 1.f / 1048576.f;
  float mu0 = g_sums[0] * invN;
  float rs0 = rsqrtf(g_sums[1] * invN - mu0 * mu0 + EPS);
  float mu1 = g_sums[2] * invN;
  float rs1 = rsqrtf(g_sums[3] * invN - mu1 * mu1 + EPS);
  for (int e = t; e < 4096; e += 128) w1s[e >> 6][e & 63] = w1[e];
  for (int e = t; e < 2048; e += 128) {
    int c = e >> 6, i = e & 63;
    float v = g_fe3[b * 2048 + e];
    xsT[i][c] = (c < 16) ? (v - mu0) * rs0 : (v - mu1) * rs1;
  }
  __syncthreads();
  float acc[4][4];
#pragma unroll
  for (int x = 0; x < 4; x++)
#pragma unroll
    for (int y = 0; y < 4; y++) acc[x][y] = 0.f;
#pragma unroll 16
  for (int kk = 0; kk < 64; kk++) {
    float4 a = *(const float4*)&xsT[kk][cg * 4];
    float4 w = *(const float4*)&w1s[kk][hg * 4];
    acc[0][0] += a.x * w.x; acc[0][1] += a.x * w.y; acc[0][2] += a.x * w.z; acc[0][3] += a.x * w.w;
    acc[1][0] += a.y * w.x; acc[1][1] += a.y * w.y; acc[1][2] += a.y * w.z; acc[1][3] += a.y * w.w;
    acc[2][0] += a.z * w.x; acc[2][1] += a.z * w.y; acc[2][2] += a.z * w.z; acc[2][3] += a.z * w.w;
    acc[3][0] += a.w * w.x; acc[3][1] += a.w * w.y; acc[3][2] += a.w * w.z; acc[3][3] += a.w * w.w;
  }
  int h0 = hg * 4;
  float4 b1v = *(const float4*)&b1[h0];
  float4 ggv = *(const float4*)&gg[h0];
  float4 bev = *(const float4*)&be[h0];
  float4 w2v = *(const float4*)&w2[h0];
  float b2v = b2f[0];
  float simp = 0.f, simp2 = 0.f;
#pragma unroll
  for (int x = 0; x < 4; x++) {
    float v0 = fmaxf(acc[x][0] + b1v.x, 0.f);
    float v1 = fmaxf(acc[x][1] + b1v.y, 0.f);
    float v2 = fmaxf(acc[x][2] + b1v.z, 0.f);
    float v3 = fmaxf(acc[x][3] + b1v.w, 0.f);
    float s  = v0 + v1 + v2 + v3;
    float s2 = v0 * v0 + v1 * v1 + v2 * v2 + v3 * v3;
#pragma unroll
    for (int o = 8; o; o >>= 1) {
      s  += __shfl_down_sync(0xffffffffu, s, o, 16);
      s2 += __shfl_down_sync(0xffffffffu, s2, o, 16);
    }
    s  = __shfl_sync(0xffffffffu, s, 0, 16);
    s2 = __shfl_sync(0xffffffffu, s2, 0, 16);
    float mu = s * (1.f / 64.f);
    float var = s2 * (1.f / 64.f) - mu * mu;
    float rstd = rsqrtf(var + EPS);
    float pp = ((v0 - mu) * rstd * ggv.x + bev.x) * w2v.x
             + ((v1 - mu) * rstd * ggv.y + bev.y) * w2v.y
             + ((v2 - mu) * rstd * ggv.z + bev.z) * w2v.z
             + ((v3 - mu) * rstd * ggv.w + bev.w) * w2v.w;
#pragma unroll
    for (int o = 8; o; o >>= 1) pp += __shfl_down_sync(0xffffffffu, pp, o, 16);
    if (hg == 0) {
      float val = pp + b2v;
      g_impraw[b * 32 + cg * 4 + x] = val;
      simp += val; simp2 += val * val;
    }
  }
  if (hg == 0) { impsh[cg][0] = simp; impsh[cg][1] = simp2; }
  __syncthreads();
  if (t == 0) {
    float a = 0.f, bsq = 0.f;
    for (int w = 0; w < 8; w++) { a += impsh[w][0]; bsq += impsh[w][1]; }
    atomicAdd(&g_sums[4], a);
    atomicAdd(&g_sums[5], bsq);
  }
}

// Merged: warp0 does top-8 + softmax p + sorted idx; all 256 threads scale fe3.
__global__ void k_topk() {
  int b = blockIdx.x;
  int t = threadIdx.x;  // 256
  __shared__ float imps[32];
  const float inv = 1.f / (NB * NCH);
  float mui = g_sums[4] * inv;
  float rsi = rsqrtf(g_sums[5] * inv - mui * mui + EPS);
  if (t < 32) {
    float imp = (g_impraw[b * 32 + t] - mui) * rsi;
    imps[t] = imp;
    float v = imp;
    float mx0 = 0.f;
#pragma unroll
    for (int k = 0; k < KSEL; k++) {
      float m = v; int mi = t;
#pragma unroll
      for (int o = 16; o; o >>= 1) {
        float om = __shfl_down_sync(0xffffffffu, m, o);
        int   oi = __shfl_down_sync(0xffffffffu, mi, o);
        if (om > m) { m = om; mi = oi; }
      }
      m  = __shfl_sync(0xffffffffu, m, 0);
      mi = __shfl_sync(0xffffffffu, mi, 0);
      if (k == 0) mx0 = m;
      if (t == mi) v = -1e30f;
    }
    bool chosen = (v == -1e30f);
    float e = chosen ? __expf(imp - mx0) : 0.f;
    float es = e;
#pragma unroll
    for (int o = 16; o; o >>= 1) es += __shfl_xor_sync(0xffffffffu, es, o);
    g_p[b * 32 + t] = e / es;
    unsigned bal = __ballot_sync(0xffffffffu, chosen);
    if (chosen) {
      int rank = __popc(bal & ((1u << t) - 1u));
      g_idx[b * KSEL + rank] = t;   // ascending by construction
    }
  }
  __syncthreads();
  const float invN = 1.f / 1048576.f;
  float mu0 = g_sums[0] * invN;
  float rs0 = rsqrtf(g_sums[1] * invN - mu0 * mu0 + EPS);
  float mu1 = g_sums[2] * invN;
  float rs1 = rsqrtf(g_sums[3] * invN - mu1 * mu1 + EPS);
  float4* p4 = (float4*)&g_fe3[b * 2048];
#pragma unroll
  for (int k = 0; k < 2; k++) {
    int q4 = t + k * 256;                  // 0..511
    float impv = imps[q4 >> 4];
    float mu = (q4 < 256) ? mu0 : mu1;
    float rs = (q4 < 256) ? rs0 : rs1;
    float4 x = p4[q4];
    x.x = (x.x - mu) * rs * impv;
    x.y = (x.y - mu) * rs * impv;
    x.z = (x.z - mu) * rs * impv;
    x.w = (x.w - mu) * rs * impv;
    p4[q4] = x;
  }
}

// ---------------- shared GEMM body on raw shared pointers -------------------
__device__ __forceinline__ void gemm_run(const float* __restrict__ A, int lda, int Kd,
                                         const float* __restrict__ W,
                                         int m, int y, int slab, int stride,
                                         float* __restrict__ As, float* __restrict__ Ws) {
  int t = threadIdx.x;      // 256
  int m0 = m * 64;
  int r0 = (t >> 4) * 4;
  int c0 = (t & 15) * 4;
  float acc[4][4];
#pragma unroll
  for (int x = 0; x < 4; x++)
#pragma unroll
    for (int yy = 0; yy < 4; yy++) acc[x][yy] = 0.f;
  for (int ch = y; ch * 64 < Kd; ch += stride) {
    int k0 = ch * 64;
    for (int e = t; e < 4096; e += 256) {
      int r = e >> 6, kk = e & 63;
      As[r * 65 + kk] = A[(size_t)(m0 + r) * lda + k0 + kk];
      Ws[r * 68 + kk] = W[(size_t)(k0 + r) * 64 + kk];
    }
    __syncthreads();
#pragma unroll 8
    for (int kk = 0; kk < 64; kk++) {
      float a0 = As[r0 * 65 + kk], a1 = As[(r0 + 1) * 65 + kk];
      float a2 = As[(r0 + 2) * 65 + kk], a3 = As[(r0 + 3) * 65 + kk];
      float4 w = *(const float4*)&Ws[kk * 68 + c0];
      acc[0][0] += a0 * w.x; acc[0][1] += a0 * w.y; acc[0][2] += a0 * w.z; acc[0][3] += a0 * w.w;
      acc[1][0] += a1 * w.x; acc[1][1] += a1 * w.y; acc[1][2] += a1 * w.z; acc[1][3] += a1 * w.w;
      acc[2][0] += a2 * w.x; acc[2][1] += a2 * w.y; acc[2][2] += a2 * w.z; acc[2][3] += a2 * w.w;
      acc[3][0] += a3 * w.x; acc[3][1] += a3 * w.y; acc[3][2] += a3 * w.z; acc[3][3] += a3 * w.w;
    }
    __syncthreads();
  }
  float* dst = &g_part[(size_t)slab * (NB * NH)];
#pragma unroll
  for (int x = 0; x < 4; x++)
#pragma unroll
    for (int yy = 0; yy < 4; yy++)
      dst[(size_t)(m0 + r0 + x) * 64 + c0 + yy] = acc[x][yy];
}

// Parallel ordered compaction body (256 threads).
__device__ __forceinline__ void compact_run(int c, int* wcnt, unsigned* ball) {
  int t = threadIdx.x;
  int w = t >> 5, lane = t & 31;
  int cnt = 0;
#pragma unroll
  for (int s = 0; s < 4; s++) {
    int b = w * 128 + s * 32 + lane;
    bool sel = false;
#pragma unroll
    for (int k = 0; k < KSEL; k++) sel |= (g_idx[b * KSEL + k] == c);
    unsigned m = __ballot_sync(0xffffffffu, sel);
    if (lane == 0) ball[w * 4 + s] = m;
    cnt += __popc(m);
  }
  if (lane == 0) wcnt[w] = cnt;
  __syncthreads();
  int base = 0;
  for (int ww = 0; ww < w; ww++) base += wcnt[ww];
#pragma unroll
  for (int s = 0; s < 4; s++) {
    int b = w * 128 + s * 32 + lane;
    unsigned m = ball[w * 4 + s];
    if ((m >> lane) & 1u) {
      int pos = base + __popc(m & ((1u << lane) - 1u));
      g_nodes[c * NB + pos] = b;
      g_loc[c * NB + b] = pos;
    }
    base += __popc(m);
  }
  if (t == 0) {
    int tot = 0;
    for (int ww = 0; ww < 8; ww++) tot += wcnt[ww];
    g_cnt[c] = tot;
  }
}

// F1: blocks 0-255 gemm feat->slabs0-15; 256-511 head fe3-part->slabs16-31;
//     512-543 compact.
__global__ void k_F1(const float* __restrict__ W0, const float* __restrict__ W1hi) {
  __shared__ float sh[64 * 65 + 64 * 68];
  __shared__ int wcnt[8];
  __shared__ unsigned ball[32];
  int b = blockIdx.x;
  if (b < 512) {
    const float* W = (b < 256) ? W0 : W1hi;
    int slabbase = (b < 256) ? 0 : 16;
    int bb = b & 255;
    gemm_run(g_fe3, 2048, 2048, W, bb & 15, bb >> 4, slabbase + (bb >> 4), 16,
             sh, sh + 64 * 65);
  } else {
    compact_run(b - 512, wcnt, ball);
  }
}

// ---- triangular S tile: E = exp(S) symmetric; mirror writes; atomic sums ---
__device__ __forceinline__ void S_tri(int c, int ti, int tj,
                                      float* pi, float* pj, float* zsh, float* colsh) {
  int n = g_cnt[c];
  int i0 = ti * 64, j0 = tj * 64;
  if (i0 >= n || j0 >= n) return;
  bool diag = (ti == tj);
  int t = threadIdx.x;  // 256
  if (t < 64) colsh[t] = 0.f;
  for (int e = t; e < 2048; e += 256) {
    int r = e >> 5, k2 = e & 31;
    int gi = i0 + r; if (gi >= n) gi = n - 1;
    pi[r * 33 + k2] = g_p[g_nodes[c * NB + gi] * NCH + k2];
  }
  for (int e = t; e < 2048; e += 256) {
    int r = e >> 5, k2 = e & 31;
    int gj = j0 + r; if (gj >= n) gj = n - 1;
    pj[r * 33 + k2] = g_p[g_nodes[c * NB + gj] * NCH + k2];
  }
  __syncthreads();
  int ii0 = (t >> 4) * 4;
  int jj0 = (t & 15) * 4;
  float acc[4][4];
#pragma unroll
  for (int x = 0; x < 4; x++)
#pragma unroll
    for (int y = 0; y < 4; y++) acc[x][y] = 0.f;
#pragma unroll 8
  for (int k2 = 0; k2 < 32; k2++) {
    float a[4], bb[4];
#pragma unroll
    for (int x = 0; x < 4; x++) a[x] = pi[(ii0 + x) * 33 + k2];
#pragma unroll
    for (int y = 0; y < 4; y++) bb[y] = pj[(jj0 + y) * 33 + k2];
#pragma unroll
    for (int x = 0; x < 4; x++)
#pragma unroll
      for (int y = 0; y < 4; y++) acc[x][y] += a[x] * bb[y];
  }
  float* slab = g_adj + ((size_t)c << 20);
  float rsum[4] = {0.f, 0.f, 0.f, 0.f};
  float csum[4] = {0.f, 0.f, 0.f, 0.f};
#pragma unroll
  for (int x = 0; x < 4; x++) {
    int gi = i0 + ii0 + x;
    if (gi < n) {
      float pic = pi[(ii0 + x) * 33 + c];
#pragma unroll
      for (int y = 0; y < 4; y++) {
        int gj = j0 + jj0 + y;
        if (gj < n) {
          float S = acc[x][y] - pic * pj[(jj0 + y) * 33 + c];
          float E = (gi != gj && S > 0.f) ? __expf(S) : 0.f;
          slab[(size_t)gi * n + gj] = E;
          rsum[x] += E;
          if (!diag) {
            slab[(size_t)gj * n + gi] = E;
            csum[y] += E;
          }
        }
      }
    }
  }
  float zloc = 0.f;
#pragma unroll
  for (int x = 0; x < 4; x++) {
#pragma unroll
    for (int o = 8; o; o >>= 1) rsum[x] += __shfl_down_sync(0xffffffffu, rsum[x], o, 16);
    if ((t & 15) == 0) {
      int gi = i0 + ii0 + x;
      if (gi < n) { atomicAdd(&g_rowsum[c * NB + gi], rsum[x]); zloc += rsum[x]; }
    }
  }
  if (!diag) {
#pragma unroll
    for (int y = 0; y < 4; y++)
      if (csum[y] != 0.f) atomicAdd(&colsh[jj0 + y], csum[y]);
  }
  if ((t & 15) == 0) zsh[t >> 4] = zloc;
  __syncthreads();
  if (!diag && t < 64) {
    int gj = j0 + t;
    if (gj < n && colsh[t] != 0.f) atomicAdd(&g_rowsum[c * NB + gj], colsh[t]);
  }
  if (t == 0) {
    float z = 0.f;
    for (int w = 0; w < 16; w++) z += zsh[w];
    atomicAdd(&g_Z[c], diag ? z : 2.f * z);
  }
}

// F2: blocks 0-63 reduce feat partials -> g_Y; blocks 64.. triangular k_S.
// 136 tile-pairs (ti<=tj, 16 tiles) per channel.
__global__ void k_F2() {
  __shared__ float pish[64 * 33];
  __shared__ float pjsh[64 * 33];
  __shared__ float zsh[16];
  __shared__ float colsh[64];
  int b = blockIdx.x;
  if (b < 64) {
    for (int e = b * 256 + threadIdx.x; e < NB * NH; e += 64 * 256) {
      float s = 0.f;
#pragma unroll
      for (int sp = 0; sp < 16; sp++) s += g_part[(size_t)sp * (NB * NH) + e];
      g_Y[e] = s;
    }
  } else {
    int idx = b - 64;
    int c = idx / 136;
    int p = idx % 136;
    int ti = 0;
    while (p >= 16 - ti) { p -= 16 - ti; ti++; }
    int tj = ti + p;
    S_tri(c, ti, tj, pish, pjsh, zsh, colsh);
  }
}

// An = E*invZ*di*dj (+ diag di^2) streamed in place; dinv computed on the fly.
__global__ void k_An() {
  int c = blockIdx.y;
  int n = g_cnt[c];
  int i = blockIdx.x;
  if (i >= n) return;
  float Z = g_Z[c];
  float invZ = (Z > 0.f) ? 1.f / Z : 1.f;
  float di = rsqrtf(1.f + g_rowsum[c * NB + i] * invZ);
  float fi = di * invZ;
  float* row = g_adj + ((size_t)c << 20) + (size_t)i * n;
  for (int j = threadIdx.x; j < n; j += 128) {
    float dj = rsqrtf(1.f + g_rowsum[c * NB + j] * invZ);
    float v = row[j] * fi * dj;
    if (j == i) v += di * di;
    row[j] = v;
  }
}

// GCN layer 1: X1[i,h] = relu(sum_j An[i,j]*Y[nodes[j],h] + bias[h]); stats1.
__global__ void k_gcn(const float* __restrict__ bias) {
  int c = blockIdx.y;
  int n = g_cnt[c];
  int i0 = blockIdx.x * 64;
  if (i0 >= n) return;
  __shared__ float As[64][65];
  __shared__ float Bs[64][68];
  int t = threadIdx.x;
  int r0 = (t >> 4) * 4, c0 = (t & 15) * 4;
  float acc[4][4];
#pragma unroll
  for (int x = 0; x < 4; x++)
#pragma unroll
    for (int y = 0; y < 4; y++) acc[x][y] = 0.f;
  const float* slab = g_adj + ((size_t)c << 20);
  for (int j0 = 0; j0 < n; j0 += 64) {
    for (int e = t; e < 4096; e += 256) {
      int r = e >> 6, kk = e & 63;
      int gi = i0 + r, gj = j0 + kk;
      As[r][kk] = (gi < n && gj < n) ? slab[(size_t)gi * n + gj] : 0.f;
      int jr = j0 + r;
      Bs[r][kk] = (jr < n) ? g_Y[g_nodes[c * NB + jr] * 64 + kk] : 0.f;
    }
    __syncthreads();
#pragma unroll 8
    for (int kk = 0; kk < 64; kk++) {
      float a0 = As[r0][kk], a1 = As[r0 + 1][kk], a2 = As[r0 + 2][kk], a3 = As[r0 + 3][kk];
      float4 w = *(const float4*)&Bs[kk][c0];
      acc[0][0] += a0 * w.x; acc[0][1] += a0 * w.y; acc[0][2] += a0 * w.z; acc[0][3] += a0 * w.w;
      acc[1][0] += a1 * w.x; acc[1][1] += a1 * w.y; acc[1][2] += a1 * w.z; acc[1][3] += a1 * w.w;
      acc[2][0] += a2 * w.x; acc[2][1] += a2 * w.y; acc[2][2] += a2 * w.z; acc[2][3] += a2 * w.w;
      acc[3][0] += a3 * w.x; acc[3][1] += a3 * w.y; acc[3][2] += a3 * w.z; acc[3][3] += a3 * w.w;
    }
    __syncthreads();
  }
  float s = 0.f, s2 = 0.f;
#pragma unroll
  for (int x = 0; x < 4; x++) {
    int gi = i0 + r0 + x;
    if (gi < n) {
#pragma unroll
      for (int y = 0; y < 4; y++) {
        float v = fmaxf(acc[x][y] + bias[c0 + y], 0.f);
        g_X1[((size_t)c * NB + gi) * 64 + c0 + y] = v;
        s += v; s2 += v * v;
      }
    }
  }
#pragma unroll
  for (int o = 16; o; o >>= 1) {
    s  += __shfl_down_sync(0xffffffffu, s, o);
    s2 += __shfl_down_sync(0xffffffffu, s2, o);
  }
  __shared__ float red[16];
  if ((t & 31) == 0) { red[(t >> 5) * 2] = s; red[(t >> 5) * 2 + 1] = s2; }
  __syncthreads();
  if (t == 0) {
    float ts = 0.f, ts2 = 0.f;
    for (int w = 0; w < 8; w++) { ts += red[w * 2]; ts2 += red[w * 2 + 1]; }
    atomicAdd(&g_stats1[c * 2], ts);
    atomicAdd(&g_stats1[c * 2 + 1], ts2);
  }
}

// GCN layer 2 fused: M = An @ LN1(X1)  (LN1 elementwise in loader),
// then X2 = relu(M @ W2 + bias) in smem epilogue; stats2. Output -> g_T.
__global__ void k_gcn2(const float* __restrict__ W2, const float* __restrict__ bias) {
  int c = blockIdx.y;
  int n = g_cnt[c];
  int i0 = blockIdx.x * 64;
  if (i0 >= n) return;
  __shared__ float As[64 * 65];
  __shared__ float Bs[64 * 68];
  int t = threadIdx.x;
  int r0 = (t >> 4) * 4, c0 = (t & 15) * 4;
  float cntf = (float)n * 64.f;
  float mu = g_stats1[c * 2] / cntf;
  float var = g_stats1[c * 2 + 1] / cntf - mu * mu;
  float rstd = rsqrtf(var + EPS);
  float acc[4][4];
#pragma unroll
  for (int x = 0; x < 4; x++)
#pragma unroll
    for (int y = 0; y < 4; y++) acc[x][y] = 0.f;
  const float* slab = g_adj + ((size_t)c << 20);
  for (int j0 = 0; j0 < n; j0 += 64) {
    for (int e = t; e < 4096; e += 256) {
      int r = e >> 6, kk = e & 63;
      int gi = i0 + r, gj = j0 + kk;
      As[r * 65 + kk] = (gi < n && gj < n) ? slab[(size_t)gi * n + gj] : 0.f;
      int jr = j0 + r;
      Bs[r * 68 + kk] = (jr < n)
        ? (g_X1[((size_t)c * NB + jr) * 64 + kk] - mu) * rstd : 0.f;
    }
    __syncthreads();
#pragma unroll 8
    for (int kk = 0; kk < 64; kk++) {
      float a0 = As[r0 * 65 + kk], a1 = As[(r0 + 1) * 65 + kk];
      float a2 = As[(r0 + 2) * 65 + kk], a3 = As[(r0 + 3) * 65 + kk];
      float4 w = *(const float4*)&Bs[kk * 68 + c0];
      acc[0][0] += a0 * w.x; acc[0][1] += a0 * w.y; acc[0][2] += a0 * w.z; acc[0][3] += a0 * w.w;
      acc[1][0] += a1 * w.x; acc[1][1] += a1 * w.y; acc[1][2] += a1 * w.z; acc[1][3] += a1 * w.w;
      acc[2][0] += a2 * w.x; acc[2][1] += a2 * w.y; acc[2][2] += a2 * w.z; acc[2][3] += a2 * w.w;
      acc[3][0] += a3 * w.x; acc[3][1] += a3 * w.y; acc[3][2] += a3 * w.z; acc[3][3] += a3 * w.w;
    }
    __syncthreads();
  }
  // epilogue: stage M in As, W2 in Bs, compute X2 = relu(M@W2 + bias)
#pragma unroll
  for (int x = 0; x < 4; x++)
#pragma unroll
    for (int y = 0; y < 4; y++)
      As[(r0 + x) * 65 + c0 + y] = acc[x][y];
  for (int e = t; e < 4096; e += 256)
    Bs[(e >> 6) * 68 + (e & 63)] = W2[e];
  __syncthreads();
  float acc2[4][4];
#pragma unroll
  for (int x = 0; x < 4; x++)
#pragma unroll
    for (int y = 0; y < 4; y++) acc2[x][y] = 0.f;
#pragma unroll 8
  for (int kk = 0; kk < 64; kk++) {
    float a0 = As[r0 * 65 + kk], a1 = As[(r0 + 1) * 65 + kk];
    float a2 = As[(r0 + 2) * 65 + kk], a3 = As[(r0 + 3) * 65 + kk];
    float4 w = *(const float4*)&Bs[kk * 68 + c0];
    acc2[0][0] += a0 * w.x; acc2[0][1] += a0 * w.y; acc2[0][2] += a0 * w.z; acc2[0][3] += a0 * w.w;
    acc2[1][0] += a1 * w.x; acc2[1][1] += a1 * w.y; acc2[1][2] += a1 * w.z; acc2[1][3] += a1 * w.w;
    acc2[2][0] += a2 * w.x; acc2[2][1] += a2 * w.y; acc2[2][2] += a2 * w.z; acc2[2][3] += a2 * w.w;
    acc2[3][0] += a3 * w.x; acc2[3][1] += a3 * w.y; acc2[3][2] += a3 * w.z; acc2[3][3] += a3 * w.w;
  }
  float s = 0.f, s2 = 0.f;
#pragma unroll
  for (int x = 0; x < 4; x++) {
    int gi = i0 + r0 + x;
    if (gi < n) {
#pragma unroll
      for (int y = 0; y < 4; y++) {
        float v = fmaxf(acc2[x][y] + bias[c0 + y], 0.f);
        g_T[((size_t)c * NB + gi) * 64 + c0 + y] = v;
        s += v; s2 += v * v;
      }
    }
  }
#pragma unroll
  for (int o = 16; o; o >>= 1) {
    s  += __shfl_down_sync(0xffffffffu, s, o);
    s2 += __shfl_down_sync(0xffffffffu, s2, o);
  }
  __shared__ float red[16];
  if ((t & 31) == 0) { red[(t >> 5) * 2] = s; red[(t >> 5) * 2 + 1] = s2; }
  __syncthreads();
  if (t == 0) {
    float ts = 0.f, ts2 = 0.f;
    for (int w = 0; w < 8; w++) { ts += red[w * 2]; ts2 += red[w * 2 + 1]; }
    atomicAdd(&g_stats2[c * 2], ts);
    atomicAdd(&g_stats2[c * 2 + 1], ts2);
  }
}

// gathered-part head GEMM with LN2+gather fused in the A loader. slabs 0-7.
__global__ void k_gemm_gath(const float* __restrict__ W) {
  __shared__ float As[64 * 65];
  __shared__ float Ws[64 * 68];
  __shared__ float mu2s[32], rs2s[32];
  int t = threadIdx.x;      // 256
  if (t < 32) {
    float cntf = (float)g_cnt[t] * 64.f;
    float mu = g_stats2[t * 2] / cntf;
    float var = g_stats2[t * 2 + 1] / cntf - mu * mu;
    mu2s[t] = mu;
    rs2s[t] = rsqrtf(var + EPS);
  }
  __syncthreads();
  int m0 = blockIdx.x * 64;
  int k0 = blockIdx.y * 64;   // one chunk per block (Kd=512, 8 slabs)
  int kq = k0 >> 6;           // which of the 8 gathered channel slots
  int r0 = (t >> 4) * 4;
  int c0 = (t & 15) * 4;
  float acc[4][4];
#pragma unroll
  for (int x = 0; x < 4; x++)
#pragma unroll
    for (int y = 0; y < 4; y++) acc[x][y] = 0.f;
  for (int e = t; e < 4096; e += 256) {
    int r = e >> 6, kk = e & 63;
    int b = m0 + r;
    int c = g_idx[b * 8 + kq];
    int ip = g_loc[c * NB + b];
    As[r * 65 + kk] = (g_T[((size_t)c * NB + ip) * 64 + kk] - mu2s[c]) * rs2s[c];
    Ws[r * 68 + kk] = W[(size_t)(k0 + r) * 64 + kk];
  }
  __syncthreads();
#pragma unroll 8
  for (int kk = 0; kk < 64; kk++) {
    float a0 = As[r0 * 65 + kk], a1 = As[(r0 + 1) * 65 + kk];
    float a2 = As[(r0 + 2) * 65 + kk], a3 = As[(r0 + 3) * 65 + kk];
    float4 w = *(const float4*)&Ws[kk * 68 + c0];
    acc[0][0] += a0 * w.x; acc[0][1] += a0 * w.y; acc[0][2] += a0 * w.z; acc[0][3] += a0 * w.w;
    acc[1][0] += a1 * w.x; acc[1][1] += a1 * w.y; acc[1][2] += a1 * w.z; acc[1][3] += a1 * w.w;
    acc[2][0] += a2 * w.x; acc[2][1] += a2 * w.y; acc[2][2] += a2 * w.z; acc[2][3] += a2 * w.w;
    acc[3][0] += a3 * w.x; acc[3][1] += a3 * w.y; acc[3][2] += a3 * w.z; acc[3][3] += a3 * w.w;
  }
  float* dst = &g_part[(size_t)blockIdx.y * (NB * NH)];
#pragma unroll
  for (int x = 0; x < 4; x++)
#pragma unroll
    for (int y = 0; y < 4; y++)
      dst[(size_t)(m0 + r0 + x) * 64 + c0 + y] = acc[x][y];
}

// head: sum hfe slabs (16-31) + gath slabs (0-7), then LN head.
__global__ void k_head(const float* __restrict__ pb1, const float* __restrict__ pg,
                       const float* __restrict__ pbe, const float* __restrict__ pw2,
                       const float* __restrict__ pb2, float* __restrict__ out) {
  int b = blockIdx.x, t = threadIdx.x;  // 64
  int e = b * 64 + t;
  float acc = 0.f;
#pragma unroll
  for (int sp = 16; sp < 32; sp++) acc += g_part[(size_t)sp * (NB * NH) + e];
#pragma unroll
  for (int sp = 0; sp < 8; sp++) acc += g_part[(size_t)sp * (NB * NH) + e];
  float v = fmaxf(acc + pb1[t], 0.f);
  float s = v, s2 = v * v;
#pragma unroll
  for (int o = 16; o; o >>= 1) {
    s  += __shfl_down_sync(0xffffffffu, s, o);
    s2 += __shfl_down_sync(0xffffffffu, s2, o);
  }
  __shared__ float red[4];
  __shared__ float red2[4];
  if ((t & 31) == 0) { red[(t >> 5) * 2] = s; red[(t >> 5) * 2 + 1] = s2; }
  __syncthreads();
  float mu = (red[0] + red[2]) * (1.f / 64.f);
  float var = (red[1] + red[3]) * (1.f / 64.f) - mu * mu;
  float rstd = rsqrtf(var + EPS);
  float hn = (v - mu) * rstd * pg[t] + pbe[t];
  float o0 = hn * pw2[t * 2];
  float o1 = hn * pw2[t * 2 + 1];
#pragma unroll
  for (int o = 16; o; o >>= 1) {
    o0 += __shfl_down_sync(0xffffffffu, o0, o);
    o1 += __shfl_down_sync(0xffffffffu, o1, o);
  }
  if ((t & 31) == 0) { red2[(t >> 5) * 2] = o0; red2[(t >> 5) * 2 + 1] = o1; }
  __syncthreads();
  if (t == 0) {
    out[b * 2]     = red2[0] + red2[2] + pb2[0];
    out[b * 2 + 1] = red2[1] + red2[3] + pb2[1];
  }
}

// ---------------------------------------------------------------------------
extern "C" void kernel_launch(void* const* d_in, const int* in_sizes, int n_in,
                              void* d_out, int out_size) {
  const float* num_data = (const float*)d_in[0];
  const int*   cat_data = (const int*)d_in[1];
  const float* num_w    = (const float*)d_in[2];
  const float* num_b    = (const float*)d_in[3];
  const float* cat_emb  = (const float*)d_in[4];
  const float* fi_w1    = (const float*)d_in[5];
  const float* fi_b1    = (const float*)d_in[6];
  const float* fi_g     = (const float*)d_in[7];
  const float* fi_be    = (const float*)d_in[8];
  const float* fi_w2    = (const float*)d_in[9];
  const float* fi_b2    = (const float*)d_in[10];
  const float* gcn1_w   = (const float*)d_in[11];
  const float* gcn1_b   = (const float*)d_in[12];
  const float* gcn2_w   = (const float*)d_in[13];
  const float* gcn2_b   = (const float*)d_in[14];
  const float* pw1      = (const float*)d_in[15];
  const float* pb1      = (const float*)d_in[16];
  const float* pg       = (const float*)d_in[17];
  const float* pbe      = (const float*)d_in[18];
  const float* pw2      = (const float*)d_in[19];
  const float* pb2      = (const float*)d_in[20];

  k_init<<<128, 256>>>();
  k_fe<<<2048, 256>>>(num_data, cat_data, num_w, num_b, cat_emb);
  k_interact<<<1024, 128>>>(fi_w1, fi_b1, fi_g, fi_be, fi_w2, fi_b2);
  k_topk<<<1024, 256>>>();
  k_F1<<<544, 256>>>(gcn1_w, pw1 + 512 * 64);
  k_F2<<<64 + 32 * 136, 256>>>();
  k_An<<<dim3(1024, 32), 128>>>();
  k_gcn<<<dim3(16, 32), 256>>>(gcn1_b);
  k_gcn2<<<dim3(16, 32), 256>>>(gcn2_w, gcn2_b);
  k_gemm_gath<<<dim3(16, 8), 256>>>(pw1);
  k_head<<<1024, 64>>>(pb1, pg, pbe, pw2, pb2, (float*)d_out);
}

// round 17
// speedup vs baseline: 1.2943x; 1.1073x over previous
#include <cuda_runtime.h>
#include <cuda_bf16.h>
#include <math.h>

#define NB   1024
#define NNUM 16
#define NCAT 16
#define NCH  32
#define NH   64
#define NV   100
#define KSEL 8
#define EPS  1e-5f

// ---------------- scratch (static device globals; no allocs) ----------------
__device__ float g_fe3[NB * NCH * NH];            // 8MB
__device__ float g_impraw[NB * NCH];
__device__ float g_p[NB * NCH];
__device__ int   g_idx[NB * KSEL];
__device__ int   g_cnt[NCH];
__device__ int   g_nodes[NCH * NB];
__device__ int   g_loc[NCH * NB];
__device__ float g_Y[NB * NH];
__device__ float g_adj[(size_t)NCH * NB * NB];    // slab: E=exp(S) -> An (in place)
__device__ float g_rowsum[NCH * NB];
__device__ float g_Z[NCH];
__device__ float g_X1[NCH * NB * NH];             // GCN layer-1 output (post-relu)
__device__ float g_T[NCH * NB * NH];              // GCN layer-2 output X2 (post-relu)
__device__ float g_stats1[NCH * 2];
__device__ float g_stats2[NCH * 2];
__device__ float g_sums[8];
__device__ float g_part[32 * NB * NH];            // 8MB split-K partial slabs

// ---------------------------------------------------------------------------
__global__ void k_init() {
  int gt = blockIdx.x * 256 + threadIdx.x;
  if (gt < 8) g_sums[gt] = 0.f;
  if (gt < NCH) { g_cnt[gt] = 0; g_Z[gt] = 0.f; }
  if (gt < NCH * 2) { g_stats1[gt] = 0.f; g_stats2[gt] = 0.f; }
  if (gt < NCH * NB) g_rowsum[gt] = 0.f;
}

__global__ void k_fe(const float* __restrict__ num_data, const int* __restrict__ cat_data,
                     const float* __restrict__ num_w, const float* __restrict__ num_b,
                     const float* __restrict__ cat_emb) {
  int t = threadIdx.x;
  int b = blockIdx.x >> 1;
  int half = blockIdx.x & 1;
  float s = 0.f, s2 = 0.f;
#pragma unroll
  for (int q = 0; q < 4; q++) {
    int off = t + q * 256;
    int ch = off >> 6, h = off & 63;
    float v;
    if (half == 0) {
      v = num_data[b * NNUM + ch] * num_w[ch * NH + h] + num_b[ch * NH + h];
      v = fmaxf(v, 0.f);
    } else {
      v = cat_emb[((size_t)ch * NV + cat_data[b * NCAT + ch]) * NH + h];
    }
    g_fe3[b * 2048 + half * 1024 + off] = v;
    s += v; s2 += v * v;
  }
#pragma unroll
  for (int o = 16; o; o >>= 1) {
    s  += __shfl_down_sync(0xffffffffu, s, o);
    s2 += __shfl_down_sync(0xffffffffu, s2, o);
  }
  __shared__ float red[16];
  if ((t & 31) == 0) { red[(t >> 5) * 2] = s; red[(t >> 5) * 2 + 1] = s2; }
  __syncthreads();
  if (t == 0) {
    float ts = 0.f, ts2 = 0.f;
    for (int w = 0; w < 8; w++) { ts += red[w * 2]; ts2 += red[w * 2 + 1]; }
    atomicAdd(&g_sums[half * 2], ts);
    atomicAdd(&g_sums[half * 2 + 1], ts2);
  }
}

// Register-tiled interact (one row b per block, 128 threads, 4x4 micro-tile).
__global__ void k_interact(const float* __restrict__ w1, const float* __restrict__ b1,
                           const float* __restrict__ gg, const float* __restrict__ be,
                           const float* __restrict__ w2, const float* __restrict__ b2f) {
  int b = blockIdx.x;
  int t = threadIdx.x;             // 128
  int cg = t >> 4, hg = t & 15;
  __shared__ float xsT[64][36];
  __shared__ float w1s[64][68];
  __shared__ float impsh[8][2];
  const float invN = 1.f / 1048576.f;
  float mu0 = g_sums[0] * invN;
  float rs0 = rsqrtf(g_sums[1] * invN - mu0 * mu0 + EPS);
  float mu1 = g_sums[2] * invN;
  float rs1 = rsqrtf(g_sums[3] * invN - mu1 * mu1 + EPS);
  for (int e = t; e < 4096; e += 128) w1s[e >> 6][e & 63] = w1[e];
  for (int e = t; e < 2048; e += 128) {
    int c = e >> 6, i = e & 63;
    float v = g_fe3[b * 2048 + e];
    xsT[i][c] = (c < 16) ? (v - mu0) * rs0 : (v - mu1) * rs1;
  }
  __syncthreads();
  float acc[4][4];
#pragma unroll
  for (int x = 0; x < 4; x++)
#pragma unroll
    for (int y = 0; y < 4; y++) acc[x][y] = 0.f;
#pragma unroll 16
  for (int kk = 0; kk < 64; kk++) {
    float4 a = *(const float4*)&xsT[kk][cg * 4];
    float4 w = *(const float4*)&w1s[kk][hg * 4];
    acc[0][0] += a.x * w.x; acc[0][1] += a.x * w.y; acc[0][2] += a.x * w.z; acc[0][3] += a.x * w.w;
    acc[1][0] += a.y * w.x; acc[1][1] += a.y * w.y; acc[1][2] += a.y * w.z; acc[1][3] += a.y * w.w;
    acc[2][0] += a.z * w.x; acc[2][1] += a.z * w.y; acc[2][2] += a.z * w.z; acc[2][3] += a.z * w.w;
    acc[3][0] += a.w * w.x; acc[3][1] += a.w * w.y; acc[3][2] += a.w * w.z; acc[3][3] += a.w * w.w;
  }
  int h0 = hg * 4;
  float4 b1v = *(const float4*)&b1[h0];
  float4 ggv = *(const float4*)&gg[h0];
  float4 bev = *(const float4*)&be[h0];
  float4 w2v = *(const float4*)&w2[h0];
  float b2v = b2f[0];
  float simp = 0.f, simp2 = 0.f;
#pragma unroll
  for (int x = 0; x < 4; x++) {
    float v0 = fmaxf(acc[x][0] + b1v.x, 0.f);
    float v1 = fmaxf(acc[x][1] + b1v.y, 0.f);
    float v2 = fmaxf(acc[x][2] + b1v.z, 0.f);
    float v3 = fmaxf(acc[x][3] + b1v.w, 0.f);
    float s  = v0 + v1 + v2 + v3;
    float s2 = v0 * v0 + v1 * v1 + v2 * v2 + v3 * v3;
#pragma unroll
    for (int o = 8; o; o >>= 1) {
      s  += __shfl_down_sync(0xffffffffu, s, o, 16);
      s2 += __shfl_down_sync(0xffffffffu, s2, o, 16);
    }
    s  = __shfl_sync(0xffffffffu, s, 0, 16);
    s2 = __shfl_sync(0xffffffffu, s2, 0, 16);
    float mu = s * (1.f / 64.f);
    float var = s2 * (1.f / 64.f) - mu * mu;
    float rstd = rsqrtf(var + EPS);
    float pp = ((v0 - mu) * rstd * ggv.x + bev.x) * w2v.x
             + ((v1 - mu) * rstd * ggv.y + bev.y) * w2v.y
             + ((v2 - mu) * rstd * ggv.z + bev.z) * w2v.z
             + ((v3 - mu) * rstd * ggv.w + bev.w) * w2v.w;
#pragma unroll
    for (int o = 8; o; o >>= 1) pp += __shfl_down_sync(0xffffffffu, pp, o, 16);
    if (hg == 0) {
      float val = pp + b2v;
      g_impraw[b * 32 + cg * 4 + x] = val;
      simp += val; simp2 += val * val;
    }
  }
  if (hg == 0) { impsh[cg][0] = simp; impsh[cg][1] = simp2; }
  __syncthreads();
  if (t == 0) {
    float a = 0.f, bsq = 0.f;
    for (int w = 0; w < 8; w++) { a += impsh[w][0]; bsq += impsh[w][1]; }
    atomicAdd(&g_sums[4], a);
    atomicAdd(&g_sums[5], bsq);
  }
}

// Merged: warp0 does top-8 + softmax p + sorted idx; all 256 threads scale fe3.
__global__ void k_topk() {
  int b = blockIdx.x;
  int t = threadIdx.x;  // 256
  __shared__ float imps[32];
  const float inv = 1.f / (NB * NCH);
  float mui = g_sums[4] * inv;
  float rsi = rsqrtf(g_sums[5] * inv - mui * mui + EPS);
  if (t < 32) {
    float imp = (g_impraw[b * 32 + t] - mui) * rsi;
    imps[t] = imp;
    float v = imp;
    float mx0 = 0.f;
#pragma unroll
    for (int k = 0; k < KSEL; k++) {
      float m = v; int mi = t;
#pragma unroll
      for (int o = 16; o; o >>= 1) {
        float om = __shfl_down_sync(0xffffffffu, m, o);
        int   oi = __shfl_down_sync(0xffffffffu, mi, o);
        if (om > m) { m = om; mi = oi; }
      }
      m  = __shfl_sync(0xffffffffu, m, 0);
      mi = __shfl_sync(0xffffffffu, mi, 0);
      if (k == 0) mx0 = m;
      if (t == mi) v = -1e30f;
    }
    bool chosen = (v == -1e30f);
    float e = chosen ? __expf(imp - mx0) : 0.f;
    float es = e;
#pragma unroll
    for (int o = 16; o; o >>= 1) es += __shfl_xor_sync(0xffffffffu, es, o);
    g_p[b * 32 + t] = e / es;
    unsigned bal = __ballot_sync(0xffffffffu, chosen);
    if (chosen) {
      int rank = __popc(bal & ((1u << t) - 1u));
      g_idx[b * KSEL + rank] = t;   // ascending by construction
    }
  }
  __syncthreads();
  const float invN = 1.f / 1048576.f;
  float mu0 = g_sums[0] * invN;
  float rs0 = rsqrtf(g_sums[1] * invN - mu0 * mu0 + EPS);
  float mu1 = g_sums[2] * invN;
  float rs1 = rsqrtf(g_sums[3] * invN - mu1 * mu1 + EPS);
  float4* p4 = (float4*)&g_fe3[b * 2048];
#pragma unroll
  for (int k = 0; k < 2; k++) {
    int q4 = t + k * 256;                  // 0..511
    float impv = imps[q4 >> 4];
    float mu = (q4 < 256) ? mu0 : mu1;
    float rs = (q4 < 256) ? rs0 : rs1;
    float4 x = p4[q4];
    x.x = (x.x - mu) * rs * impv;
    x.y = (x.y - mu) * rs * impv;
    x.z = (x.z - mu) * rs * impv;
    x.w = (x.w - mu) * rs * impv;
    p4[q4] = x;
  }
}

// ---------------- shared GEMM body on raw shared pointers -------------------
__device__ __forceinline__ void gemm_run(const float* __restrict__ A, int lda, int Kd,
                                         const float* __restrict__ W,
                                         int m, int y, int slab, int stride,
                                         float* __restrict__ As, float* __restrict__ Ws) {
  int t = threadIdx.x;      // 256
  int m0 = m * 64;
  int r0 = (t >> 4) * 4;
  int c0 = (t & 15) * 4;
  float acc[4][4];
#pragma unroll
  for (int x = 0; x < 4; x++)
#pragma unroll
    for (int yy = 0; yy < 4; yy++) acc[x][yy] = 0.f;
  for (int ch = y; ch * 64 < Kd; ch += stride) {
    int k0 = ch * 64;
    for (int e = t; e < 4096; e += 256) {
      int r = e >> 6, kk = e & 63;
      As[r * 65 + kk] = A[(size_t)(m0 + r) * lda + k0 + kk];
      Ws[r * 68 + kk] = W[(size_t)(k0 + r) * 64 + kk];
    }
    __syncthreads();
#pragma unroll 8
    for (int kk = 0; kk < 64; kk++) {
      float a0 = As[r0 * 65 + kk], a1 = As[(r0 + 1) * 65 + kk];
      float a2 = As[(r0 + 2) * 65 + kk], a3 = As[(r0 + 3) * 65 + kk];
      float4 w = *(const float4*)&Ws[kk * 68 + c0];
      acc[0][0] += a0 * w.x; acc[0][1] += a0 * w.y; acc[0][2] += a0 * w.z; acc[0][3] += a0 * w.w;
      acc[1][0] += a1 * w.x; acc[1][1] += a1 * w.y; acc[1][2] += a1 * w.z; acc[1][3] += a1 * w.w;
      acc[2][0] += a2 * w.x; acc[2][1] += a2 * w.y; acc[2][2] += a2 * w.z; acc[2][3] += a2 * w.w;
      acc[3][0] += a3 * w.x; acc[3][1] += a3 * w.y; acc[3][2] += a3 * w.z; acc[3][3] += a3 * w.w;
    }
    __syncthreads();
  }
  float* dst = &g_part[(size_t)slab * (NB * NH)];
#pragma unroll
  for (int x = 0; x < 4; x++)
#pragma unroll
    for (int yy = 0; yy < 4; yy++)
      dst[(size_t)(m0 + r0 + x) * 64 + c0 + yy] = acc[x][yy];
}

// Parallel ordered compaction body (256 threads).
__device__ __forceinline__ void compact_run(int c, int* wcnt, unsigned* ball) {
  int t = threadIdx.x;
  int w = t >> 5, lane = t & 31;
  int cnt = 0;
#pragma unroll
  for (int s = 0; s < 4; s++) {
    int b = w * 128 + s * 32 + lane;
    bool sel = false;
#pragma unroll
    for (int k = 0; k < KSEL; k++) sel |= (g_idx[b * KSEL + k] == c);
    unsigned m = __ballot_sync(0xffffffffu, sel);
    if (lane == 0) ball[w * 4 + s] = m;
    cnt += __popc(m);
  }
  if (lane == 0) wcnt[w] = cnt;
  __syncthreads();
  int base = 0;
  for (int ww = 0; ww < w; ww++) base += wcnt[ww];
#pragma unroll
  for (int s = 0; s < 4; s++) {
    int b = w * 128 + s * 32 + lane;
    unsigned m = ball[w * 4 + s];
    if ((m >> lane) & 1u) {
      int pos = base + __popc(m & ((1u << lane) - 1u));
      g_nodes[c * NB + pos] = b;
      g_loc[c * NB + b] = pos;
    }
    base += __popc(m);
  }
  if (t == 0) {
    int tot = 0;
    for (int ww = 0; ww < 8; ww++) tot += wcnt[ww];
    g_cnt[c] = tot;
  }
}

// F1: blocks 0-255 gemm feat->slabs0-15; 256-511 head fe3-part->slabs16-31;
//     512-543 compact.
__global__ void k_F1(const float* __restrict__ W0, const float* __restrict__ W1hi) {
  __shared__ float sh[64 * 65 + 64 * 68];
  __shared__ int wcnt[8];
  __shared__ unsigned ball[32];
  int b = blockIdx.x;
  if (b < 512) {
    const float* W = (b < 256) ? W0 : W1hi;
    int slabbase = (b < 256) ? 0 : 16;
    int bb = b & 255;
    gemm_run(g_fe3, 2048, 2048, W, bb & 15, bb >> 4, slabbase + (bb >> 4), 16,
             sh, sh + 64 * 65);
  } else {
    compact_run(b - 512, wcnt, ball);
  }
}

// ---- triangular S tile: E = exp(S) symmetric; mirror writes; atomic sums ---
__device__ __forceinline__ void S_tri(int c, int ti, int tj,
                                      float* pi, float* pj, float* zsh, float* colsh) {
  int n = g_cnt[c];
  int i0 = ti * 64, j0 = tj * 64;
  if (i0 >= n || j0 >= n) return;
  bool diag = (ti == tj);
  int t = threadIdx.x;  // 256
  if (t < 64) colsh[t] = 0.f;
  for (int e = t; e < 2048; e += 256) {
    int r = e >> 5, k2 = e & 31;
    int gi = i0 + r; if (gi >= n) gi = n - 1;
    pi[r * 33 + k2] = g_p[g_nodes[c * NB + gi] * NCH + k2];
  }
  for (int e = t; e < 2048; e += 256) {
    int r = e >> 5, k2 = e & 31;
    int gj = j0 + r; if (gj >= n) gj = n - 1;
    pj[r * 33 + k2] = g_p[g_nodes[c * NB + gj] * NCH + k2];
  }
  __syncthreads();
  int ii0 = (t >> 4) * 4;
  int jj0 = (t & 15) * 4;
  float acc[4][4];
#pragma unroll
  for (int x = 0; x < 4; x++)
#pragma unroll
    for (int y = 0; y < 4; y++) acc[x][y] = 0.f;
#pragma unroll 8
  for (int k2 = 0; k2 < 32; k2++) {
    float a[4], bb[4];
#pragma unroll
    for (int x = 0; x < 4; x++) a[x] = pi[(ii0 + x) * 33 + k2];
#pragma unroll
    for (int y = 0; y < 4; y++) bb[y] = pj[(jj0 + y) * 33 + k2];
#pragma unroll
    for (int x = 0; x < 4; x++)
#pragma unroll
      for (int y = 0; y < 4; y++) acc[x][y] += a[x] * bb[y];
  }
  float* slab = g_adj + ((size_t)c << 20);
  float rsum[4] = {0.f, 0.f, 0.f, 0.f};
  float csum[4] = {0.f, 0.f, 0.f, 0.f};
#pragma unroll
  for (int x = 0; x < 4; x++) {
    int gi = i0 + ii0 + x;
    if (gi < n) {
      float pic = pi[(ii0 + x) * 33 + c];
#pragma unroll
      for (int y = 0; y < 4; y++) {
        int gj = j0 + jj0 + y;
        if (gj < n) {
          float S = acc[x][y] - pic * pj[(jj0 + y) * 33 + c];
          float E = (gi != gj && S > 0.f) ? __expf(S) : 0.f;
          slab[(size_t)gi * n + gj] = E;
          rsum[x] += E;
          if (!diag) {
            slab[(size_t)gj * n + gi] = E;
            csum[y] += E;
          }
        }
      }
    }
  }
  float zloc = 0.f;
#pragma unroll
  for (int x = 0; x < 4; x++) {
#pragma unroll
    for (int o = 8; o; o >>= 1) rsum[x] += __shfl_down_sync(0xffffffffu, rsum[x], o, 16);
    if ((t & 15) == 0) {
      int gi = i0 + ii0 + x;
      if (gi < n) { atomicAdd(&g_rowsum[c * NB + gi], rsum[x]); zloc += rsum[x]; }
    }
  }
  if (!diag) {
#pragma unroll
    for (int y = 0; y < 4; y++)
      if (csum[y] != 0.f) atomicAdd(&colsh[jj0 + y], csum[y]);
  }
  if ((t & 15) == 0) zsh[t >> 4] = zloc;
  __syncthreads();
  if (!diag && t < 64) {
    int gj = j0 + t;
    if (gj < n && colsh[t] != 0.f) atomicAdd(&g_rowsum[c * NB + gj], colsh[t]);
  }
  if (t == 0) {
    float z = 0.f;
    for (int w = 0; w < 16; w++) z += zsh[w];
    atomicAdd(&g_Z[c], diag ? z : 2.f * z);
  }
}

// F2: blocks 0-63 reduce feat partials -> g_Y; blocks 64.. triangular k_S.
__global__ void k_F2() {
  __shared__ float pish[64 * 33];
  __shared__ float pjsh[64 * 33];
  __shared__ float zsh[16];
  __shared__ float colsh[64];
  int b = blockIdx.x;
  if (b < 64) {
    for (int e = b * 256 + threadIdx.x; e < NB * NH; e += 64 * 256) {
      float s = 0.f;
#pragma unroll
      for (int sp = 0; sp < 16; sp++) s += g_part[(size_t)sp * (NB * NH) + e];
      g_Y[e] = s;
    }
  } else {
    int idx = b - 64;
    int c = idx / 136;
    int p = idx % 136;
    int ti = 0;
    while (p >= 16 - ti) { p -= 16 - ti; ti++; }
    int tj = ti + p;
    S_tri(c, ti, tj, pish, pjsh, zsh, colsh);
  }
}

// An = E*invZ*di*dj (+ diag di^2) streamed in place; dinv computed on the fly.
__global__ void k_An() {
  int c = blockIdx.y;
  int n = g_cnt[c];
  int i = blockIdx.x;
  if (i >= n) return;
  float Z = g_Z[c];
  float invZ = (Z > 0.f) ? 1.f / Z : 1.f;
  float di = rsqrtf(1.f + g_rowsum[c * NB + i] * invZ);
  float fi = di * invZ;
  float* row = g_adj + ((size_t)c << 20) + (size_t)i * n;
  for (int j = threadIdx.x; j < n; j += 128) {
    float dj = rsqrtf(1.f + g_rowsum[c * NB + j] * invZ);
    float v = row[j] * fi * dj;
    if (j == i) v += di * di;
    row[j] = v;
  }
}

// GCN layer 1, 32-row tiles (2x4 micro-tile, 256 thr): X1 = relu(An@Y + b).
__global__ void k_gcn(const float* __restrict__ bias) {
  int c = blockIdx.y;
  int n = g_cnt[c];
  int i0 = blockIdx.x * 32;
  if (i0 >= n) return;
  __shared__ float As[32 * 65];
  __shared__ float Bs[64 * 68];
  int t = threadIdx.x;
  int r0 = (t >> 4) * 2, c0 = (t & 15) * 4;
  float acc[2][4];
#pragma unroll
  for (int x = 0; x < 2; x++)
#pragma unroll
    for (int y = 0; y < 4; y++) acc[x][y] = 0.f;
  const float* slab = g_adj + ((size_t)c << 20);
  for (int j0 = 0; j0 < n; j0 += 64) {
    for (int e = t; e < 2048; e += 256) {
      int r = e >> 6, kk = e & 63;
      int gi = i0 + r, gj = j0 + kk;
      As[r * 65 + kk] = (gi < n && gj < n) ? slab[(size_t)gi * n + gj] : 0.f;
    }
    for (int e = t; e < 4096; e += 256) {
      int r = e >> 6, kk = e & 63;
      int jr = j0 + r;
      Bs[r * 68 + kk] = (jr < n) ? g_Y[g_nodes[c * NB + jr] * 64 + kk] : 0.f;
    }
    __syncthreads();
#pragma unroll 8
    for (int kk = 0; kk < 64; kk++) {
      float a0 = As[r0 * 65 + kk], a1 = As[(r0 + 1) * 65 + kk];
      float4 w = *(const float4*)&Bs[kk * 68 + c0];
      acc[0][0] += a0 * w.x; acc[0][1] += a0 * w.y; acc[0][2] += a0 * w.z; acc[0][3] += a0 * w.w;
      acc[1][0] += a1 * w.x; acc[1][1] += a1 * w.y; acc[1][2] += a1 * w.z; acc[1][3] += a1 * w.w;
    }
    __syncthreads();
  }
  float s = 0.f, s2 = 0.f;
#pragma unroll
  for (int x = 0; x < 2; x++) {
    int gi = i0 + r0 + x;
    if (gi < n) {
#pragma unroll
      for (int y = 0; y < 4; y++) {
        float v = fmaxf(acc[x][y] + bias[c0 + y], 0.f);
        g_X1[((size_t)c * NB + gi) * 64 + c0 + y] = v;
        s += v; s2 += v * v;
      }
    }
  }
#pragma unroll
  for (int o = 16; o; o >>= 1) {
    s  += __shfl_down_sync(0xffffffffu, s, o);
    s2 += __shfl_down_sync(0xffffffffu, s2, o);
  }
  __shared__ float red[16];
  if ((t & 31) == 0) { red[(t >> 5) * 2] = s; red[(t >> 5) * 2 + 1] = s2; }
  __syncthreads();
  if (t == 0) {
    float ts = 0.f, ts2 = 0.f;
    for (int w = 0; w < 8; w++) { ts += red[w * 2]; ts2 += red[w * 2 + 1]; }
    atomicAdd(&g_stats1[c * 2], ts);
    atomicAdd(&g_stats1[c * 2 + 1], ts2);
  }
}

// GCN layer 2 fused, 32-row tiles: M = An @ LN1(X1); X2 = relu(M@W2+b); stats2.
__global__ void k_gcn2(const float* __restrict__ W2, const float* __restrict__ bias) {
  int c = blockIdx.y;
  int n = g_cnt[c];
  int i0 = blockIdx.x * 32;
  if (i0 >= n) return;
  __shared__ float As[32 * 65];
  __shared__ float Bs[64 * 68];
  int t = threadIdx.x;
  int r0 = (t >> 4) * 2, c0 = (t & 15) * 4;
  float cntf = (float)n * 64.f;
  float mu = g_stats1[c * 2] / cntf;
  float var = g_stats1[c * 2 + 1] / cntf - mu * mu;
  float rstd = rsqrtf(var + EPS);
  float acc[2][4];
#pragma unroll
  for (int x = 0; x < 2; x++)
#pragma unroll
    for (int y = 0; y < 4; y++) acc[x][y] = 0.f;
  const float* slab = g_adj + ((size_t)c << 20);
  for (int j0 = 0; j0 < n; j0 += 64) {
    for (int e = t; e < 2048; e += 256) {
      int r = e >> 6, kk = e & 63;
      int gi = i0 + r, gj = j0 + kk;
      As[r * 65 + kk] = (gi < n && gj < n) ? slab[(size_t)gi * n + gj] : 0.f;
    }
    for (int e = t; e < 4096; e += 256) {
      int r = e >> 6, kk = e & 63;
      int jr = j0 + r;
      Bs[r * 68 + kk] = (jr < n)
        ? (g_X1[((size_t)c * NB + jr) * 64 + kk] - mu) * rstd : 0.f;
    }
    __syncthreads();
#pragma unroll 8
    for (int kk = 0; kk < 64; kk++) {
      float a0 = As[r0 * 65 + kk], a1 = As[(r0 + 1) * 65 + kk];
      float4 w = *(const float4*)&Bs[kk * 68 + c0];
      acc[0][0] += a0 * w.x; acc[0][1] += a0 * w.y; acc[0][2] += a0 * w.z; acc[0][3] += a0 * w.w;
      acc[1][0] += a1 * w.x; acc[1][1] += a1 * w.y; acc[1][2] += a1 * w.z; acc[1][3] += a1 * w.w;
    }
    __syncthreads();
  }
  // epilogue: stage M (32x64) in As, W2 in Bs; X2 = relu(M@W2 + bias)
#pragma unroll
  for (int x = 0; x < 2; x++)
#pragma unroll
    for (int y = 0; y < 4; y++)
      As[(r0 + x) * 65 + c0 + y] = acc[x][y];
  for (int e = t; e < 4096; e += 256)
    Bs[(e >> 6) * 68 + (e & 63)] = W2[e];
  __syncthreads();
  float acc2[2][4];
#pragma unroll
  for (int x = 0; x < 2; x++)
#pragma unroll
    for (int y = 0; y < 4; y++) acc2[x][y] = 0.f;
#pragma unroll 8
  for (int kk = 0; kk < 64; kk++) {
    float a0 = As[r0 * 65 + kk], a1 = As[(r0 + 1) * 65 + kk];
    float4 w = *(const float4*)&Bs[kk * 68 + c0];
    acc2[0][0] += a0 * w.x; acc2[0][1] += a0 * w.y; acc2[0][2] += a0 * w.z; acc2[0][3] += a0 * w.w;
    acc2[1][0] += a1 * w.x; acc2[1][1] += a1 * w.y; acc2[1][2] += a1 * w.z; acc2[1][3] += a1 * w.w;
  }
  float s = 0.f, s2 = 0.f;
#pragma unroll
  for (int x = 0; x < 2; x++) {
    int gi = i0 + r0 + x;
    if (gi < n) {
#pragma unroll
      for (int y = 0; y < 4; y++) {
        float v = fmaxf(acc2[x][y] + bias[c0 + y], 0.f);
        g_T[((size_t)c * NB + gi) * 64 + c0 + y] = v;
        s += v; s2 += v * v;
      }
    }
  }
#pragma unroll
  for (int o = 16; o; o >>= 1) {
    s  += __shfl_down_sync(0xffffffffu, s, o);
    s2 += __shfl_down_sync(0xffffffffu, s2, o);
  }
  __shared__ float red[16];
  if ((t & 31) == 0) { red[(t >> 5) * 2] = s; red[(t >> 5) * 2 + 1] = s2; }
  __syncthreads();
  if (t == 0) {
    float ts = 0.f, ts2 = 0.f;
    for (int w = 0; w < 8; w++) { ts += red[w * 2]; ts2 += red[w * 2 + 1]; }
    atomicAdd(&g_stats2[c * 2], ts);
    atomicAdd(&g_stats2[c * 2 + 1], ts2);
  }
}

// gathered-part head GEMM with LN2+gather fused in the A loader. slabs 0-7.
__global__ void k_gemm_gath(const float* __restrict__ W) {
  __shared__ float As[64 * 65];
  __shared__ float Ws[64 * 68];
  __shared__ float mu2s[32], rs2s[32];
  int t = threadIdx.x;      // 256
  if (t < 32) {
    float cntf = (float)g_cnt[t] * 64.f;
    float mu = g_stats2[t * 2] / cntf;
    float var = g_stats2[t * 2 + 1] / cntf - mu * mu;
    mu2s[t] = mu;
    rs2s[t] = rsqrtf(var + EPS);
  }
  __syncthreads();
  int m0 = blockIdx.x * 64;
  int k0 = blockIdx.y * 64;   // one chunk per block (Kd=512, 8 slabs)
  int kq = k0 >> 6;           // which of the 8 gathered channel slots
  int r0 = (t >> 4) * 4;
  int c0 = (t & 15) * 4;
  float acc[4][4];
#pragma unroll
  for (int x = 0; x < 4; x++)
#pragma unroll
    for (int y = 0; y < 4; y++) acc[x][y] = 0.f;
  for (int e = t; e < 4096; e += 256) {
    int r = e >> 6, kk = e & 63;
    int b = m0 + r;
    int c = g_idx[b * 8 + kq];
    int ip = g_loc[c * NB + b];
    As[r * 65 + kk] = (g_T[((size_t)c * NB + ip) * 64 + kk] - mu2s[c]) * rs2s[c];
    Ws[r * 68 + kk] = W[(size_t)(k0 + r) * 64 + kk];
  }
  __syncthreads();
#pragma unroll 8
  for (int kk = 0; kk < 64; kk++) {
    float a0 = As[r0 * 65 + kk], a1 = As[(r0 + 1) * 65 + kk];
    float a2 = As[(r0 + 2) * 65 + kk], a3 = As[(r0 + 3) * 65 + kk];
    float4 w = *(const float4*)&Ws[kk * 68 + c0];
    acc[0][0] += a0 * w.x; acc[0][1] += a0 * w.y; acc[0][2] += a0 * w.z; acc[0][3] += a0 * w.w;
    acc[1][0] += a1 * w.x; acc[1][1] += a1 * w.y; acc[1][2] += a1 * w.z; acc[1][3] += a1 * w.w;
    acc[2][0] += a2 * w.x; acc[2][1] += a2 * w.y; acc[2][2] += a2 * w.z; acc[2][3] += a2 * w.w;
    acc[3][0] += a3 * w.x; acc[3][1] += a3 * w.y; acc[3][2] += a3 * w.z; acc[3][3] += a3 * w.w;
  }
  float* dst = &g_part[(size_t)blockIdx.y * (NB * NH)];
#pragma unroll
  for (int x = 0; x < 4; x++)
#pragma unroll
    for (int y = 0; y < 4; y++)
      dst[(size_t)(m0 + r0 + x) * 64 + c0 + y] = acc[x][y];
}

// head: sum hfe slabs (16-31) + gath slabs (0-7), then LN head.
__global__ void k_head(const float* __restrict__ pb1, const float* __restrict__ pg,
                       const float* __restrict__ pbe, const float* __restrict__ pw2,
                       const float* __restrict__ pb2, float* __restrict__ out) {
  int b = blockIdx.x, t = threadIdx.x;  // 64
  int e = b * 64 + t;
  float acc = 0.f;
#pragma unroll
  for (int sp = 16; sp < 32; sp++) acc += g_part[(size_t)sp * (NB * NH) + e];
#pragma unroll
  for (int sp = 0; sp < 8; sp++) acc += g_part[(size_t)sp * (NB * NH) + e];
  float v = fmaxf(acc + pb1[t], 0.f);
  float s = v, s2 = v * v;
#pragma unroll
  for (int o = 16; o; o >>= 1) {
    s  += __shfl_down_sync(0xffffffffu, s, o);
    s2 += __shfl_down_sync(0xffffffffu, s2, o);
  }
  __shared__ float red[4];
  __shared__ float red2[4];
  if ((t & 31) == 0) { red[(t >> 5) * 2] = s; red[(t >> 5) * 2 + 1] = s2; }
  __syncthreads();
  float mu = (red[0] + red[2]) * (1.f / 64.f);
  float var = (red[1] + red[3]) * (1.f / 64.f) - mu * mu;
  float rstd = rsqrtf(var + EPS);
  float hn = (v - mu) * rstd * pg[t] + pbe[t];
  float o0 = hn * pw2[t * 2];
  float o1 = hn * pw2[t * 2 + 1];
#pragma unroll
  for (int o = 16; o; o >>= 1) {
    o0 += __shfl_down_sync(0xffffffffu, o0, o);
    o1 += __shfl_down_sync(0xffffffffu, o1, o);
  }
  if ((t & 31) == 0) { red2[(t >> 5) * 2] = o0; red2[(t >> 5) * 2 + 1] = o1; }
  __syncthreads();
  if (t == 0) {
    out[b * 2]     = red2[0] + red2[2] + pb2[0];
    out[b * 2 + 1] = red2[1] + red2[3] + pb2[1];
  }
}

// ---------------------------------------------------------------------------
extern "C" void kernel_launch(void* const* d_in, const int* in_sizes, int n_in,
                              void* d_out, int out_size) {
  const float* num_data = (const float*)d_in[0];
  const int*   cat_data = (const int*)d_in[1];
  const float* num_w    = (const float*)d_in[2];
  const float* num_b    = (const float*)d_in[3];
  const float* cat_emb  = (const float*)d_in[4];
  const float* fi_w1    = (const float*)d_in[5];
  const float* fi_b1    = (const float*)d_in[6];
  const float* fi_g     = (const float*)d_in[7];
  const float* fi_be    = (const float*)d_in[8];
  const float* fi_w2    = (const float*)d_in[9];
  const float* fi_b2    = (const float*)d_in[10];
  const float* gcn1_w   = (const float*)d_in[11];
  const float* gcn1_b   = (const float*)d_in[12];
  const float* gcn2_w   = (const float*)d_in[13];
  const float* gcn2_b   = (const float*)d_in[14];
  const float* pw1      = (const float*)d_in[15];
  const float* pb1      = (const float*)d_in[16];
  const float* pg       = (const float*)d_in[17];
  const float* pbe      = (const float*)d_in[18];
  const float* pw2      = (const float*)d_in[19];
  const float* pb2      = (const float*)d_in[20];

  k_init<<<128, 256>>>();
  k_fe<<<2048, 256>>>(num_data, cat_data, num_w, num_b, cat_emb);
  k_interact<<<1024, 128>>>(fi_w1, fi_b1, fi_g, fi_be, fi_w2, fi_b2);
  k_topk<<<1024, 256>>>();
  k_F1<<<544, 256>>>(gcn1_w, pw1 + 512 * 64);
  k_F2<<<64 + 32 * 136, 256>>>();
  k_An<<<dim3(1024, 32), 128>>>();
  k_gcn<<<dim3(32, 32), 256>>>(gcn1_b);
  k_gcn2<<<dim3(32, 32), 256>>>(gcn2_w, gcn2_b);
  k_gemm_gath<<<dim3(16, 8), 256>>>(pw1);
  k_head<<<1024, 64>>>(pb1, pg, pbe, pw2, pb2, (float*)d_out);
}